// round 12
// baseline (speedup 1.0000x reference)
#include <cuda_runtime.h>
#include <cuda_fp16.h>
#include <math.h>
#include <stdint.h>

#define Bb 32
#define Ll 512
#define Ee 512
#define RR (Bb*Ll)
#define KE (5*Ee)
#define EPSV 1e-3f
#define PADW 136

// fp32 scratch (pre-BN activations for exact stats)
__device__ float g_l[RR*Ee];
__device__ float g_q[RR*Ee];
__device__ float g_k[RR*Ee];
__device__ float g_w[Bb*Ll*Ll];     // wT[b,k,q] pre-BN fp32
__device__ float g_o[RR*Ee];
__device__ float g_wbT[Ll*Ll];
__device__ float g_s[10*Ee];
// fp16 operands
__device__ __half g_fh[KE*Ee];
__device__ __half g_wqh[Ee*Ee];
__device__ __half g_wkh[Ee*Ee];
__device__ __half g_lh[RR*Ee];
__device__ __half g_qh[RR*Ee];
__device__ __half g_kh[RR*Ee];
__device__ __half g_wh[Bb*Ll*Ll];

__device__ __forceinline__ uint32_t pack2(float a, float b) {
    __half2 h = __floats2half2_rn(a, b);
    return *(uint32_t*)&h;
}

// ---------------------------------------------------------------------------
// fp16 mma core: 64x64 warp tile over [16][PADW] kpair-word tiles, BK=32.
// word (kp, col) = {X[2kp][col], X[2kp+1][col]} (A: col=m; B: col=n).
// ---------------------------------------------------------------------------
__device__ __forceinline__ void mma_core64h(const uint32_t (*As)[PADW],
                                            const uint32_t (*Bs)[PADW],
                                            float c[4][8][4],
                                            int g, int t, int wm, int wn) {
    #pragma unroll
    for (int ks = 0; ks < 2; ks++) {
        const int kb = ks * 8;
        uint32_t a[4][4], b[8][2];
        #pragma unroll
        for (int mt = 0; mt < 4; mt++) {
            const int m = wm + mt * 16 + g;
            a[mt][0] = As[kb + t][m];
            a[mt][1] = As[kb + t][m + 8];
            a[mt][2] = As[kb + t + 4][m];
            a[mt][3] = As[kb + t + 4][m + 8];
        }
        #pragma unroll
        for (int nt = 0; nt < 8; nt++) {
            const int n = wn + nt * 8 + g;
            b[nt][0] = Bs[kb + t][n];
            b[nt][1] = Bs[kb + t + 4][n];
        }
        #pragma unroll
        for (int mt = 0; mt < 4; mt++)
            #pragma unroll
            for (int nt = 0; nt < 8; nt++)
                asm volatile(
                    "mma.sync.aligned.m16n8k16.row.col.f32.f16.f16.f32 "
                    "{%0,%1,%2,%3},{%4,%5,%6,%7},{%8,%9},{%0,%1,%2,%3};"
                    : "+f"(c[mt][nt][0]), "+f"(c[mt][nt][1]),
                      "+f"(c[mt][nt][2]), "+f"(c[mt][nt][3])
                    : "r"(a[mt][0]), "r"(a[mt][1]), "r"(a[mt][2]), "r"(a[mt][3]),
                      "r"(b[nt][0]), "r"(b[nt][1]));
    }
}

// m-major staging: thread col m = tid, 32 k-contig halves = 4 x uint4.
__device__ __forceinline__ void ld_mmaj(uint4 v[4], const __half* src) {
    const uint4* p = (const uint4*)src;
    v[0] = p[0]; v[1] = p[1]; v[2] = p[2]; v[3] = p[3];
}
__device__ __forceinline__ void st_mmaj(uint32_t (*S)[PADW], int m, const uint4 v[4]) {
    #pragma unroll
    for (int u = 0; u < 4; u++) {
        S[4*u + 0][m] = v[u].x;
        S[4*u + 1][m] = v[u].y;
        S[4*u + 2][m] = v[u].z;
        S[4*u + 3][m] = v[u].w;
    }
}
// fp32 m-major variant: 32 k-contig floats = 8 float4; cvt at store.
__device__ __forceinline__ void ld_mmajf(float4 v[8], const float* src) {
    const float4* p = (const float4*)src;
    #pragma unroll
    for (int j = 0; j < 8; j++) v[j] = p[j];
}
__device__ __forceinline__ void st_mmajf(uint32_t (*S)[PADW], int m, const float4 v[8]) {
    #pragma unroll
    for (int u = 0; u < 4; u++) {
        S[4*u + 0][m] = pack2(v[2*u].x, v[2*u].y);
        S[4*u + 1][m] = pack2(v[2*u].z, v[2*u].w);
        S[4*u + 2][m] = pack2(v[2*u+1].x, v[2*u+1].y);
        S[4*u + 3][m] = pack2(v[2*u+1].z, v[2*u+1].w);
    }
}
// k-major staging: thread covers colquad c0 = 4*(tid&31), kp = (tid>>5)+4j.
__device__ __forceinline__ void ld_kmaj(uint2 x[4], uint2 y[4], const __half* B,
                                        int ld, int k0, int kpb, int gcol) {
    #pragma unroll
    for (int j = 0; j < 4; j++) {
        const __half* r = B + (size_t)(k0 + 2 * (kpb + 4 * j)) * ld + gcol;
        x[j] = *(const uint2*)r;
        y[j] = *(const uint2*)(r + ld);
    }
}
__device__ __forceinline__ void st_kmaj(uint32_t (*S)[PADW], int kpb, int c0,
                                        const uint2 x[4], const uint2 y[4]) {
    #pragma unroll
    for (int j = 0; j < 4; j++) {
        const int kp = kpb + 4 * j;
        uint4 w;
        w.x = __byte_perm(x[j].x, y[j].x, 0x5410);
        w.y = __byte_perm(x[j].x, y[j].x, 0x7632);
        w.z = __byte_perm(x[j].y, y[j].y, 0x5410);
        w.w = __byte_perm(x[j].y, y[j].y, 0x7632);
        *(uint4*)&S[kp][c0] = w;
    }
}

__device__ __forceinline__ void colstats_epilogue(float* __restrict__ sum,
                                                  float* __restrict__ sumsq,
                                                  const float cs[16], const float cq[16],
                                                  int g, int t, int bcwn) {
    #pragma unroll
    for (int x = 0; x < 16; x++) {
        float s = cs[x], q = cq[x];
        s += __shfl_xor_sync(0xffffffffu, s, 4);  q += __shfl_xor_sync(0xffffffffu, q, 4);
        s += __shfl_xor_sync(0xffffffffu, s, 8);  q += __shfl_xor_sync(0xffffffffu, q, 8);
        s += __shfl_xor_sync(0xffffffffu, s, 16); q += __shfl_xor_sync(0xffffffffu, q, 16);
        if (g == 0) {
            const int col = bcwn + (x >> 1) * 8 + 2 * t + (x & 1);
            atomicAdd(&sum[col], s);
            atomicAdd(&sumsq[col], q);
        }
    }
}
__device__ __forceinline__ float blockReduceSum(float v, float* sh) {
    const int t = threadIdx.x;
    #pragma unroll
    for (int o = 16; o > 0; o >>= 1) v += __shfl_xor_sync(0xffffffffu, v, o);
    if ((t & 31) == 0) sh[t >> 5] = v;
    __syncthreads();
    if (t < 32) {
        v = (t < (int)(blockDim.x >> 5)) ? sh[t] : 0.f;
        #pragma unroll
        for (int o = 16; o > 0; o >>= 1) v += __shfl_xor_sync(0xffffffffu, v, o);
        if (t == 0) sh[0] = v;
    }
    __syncthreads();
    float r = sh[0];
    __syncthreads();
    return r;
}
__device__ __forceinline__ float blockReduceMax(float v, float* sh) {
    const int t = threadIdx.x;
    #pragma unroll
    for (int o = 16; o > 0; o >>= 1) v = fmaxf(v, __shfl_xor_sync(0xffffffffu, v, o));
    if ((t & 31) == 0) sh[t >> 5] = v;
    __syncthreads();
    if (t < 32) {
        v = (t < (int)(blockDim.x >> 5)) ? sh[t] : -INFINITY;
        #pragma unroll
        for (int o = 16; o > 0; o >>= 1) v = fmaxf(v, __shfl_xor_sync(0xffffffffu, v, o));
        if (t == 0) sh[0] = v;
    }
    __syncthreads();
    float r = sh[0];
    __syncthreads();
    return r;
}

__global__ void k_zero(float* p, int n) {
    int i = blockIdx.x * blockDim.x + threadIdx.x;
    if (i < n) p[i] = 0.f;
}
__global__ void k_transpose(const float* __restrict__ src, float* __restrict__ dst) {
    __shared__ float tile[32][33];
    const int bx = blockIdx.x << 5, by = blockIdx.y << 5;
    #pragma unroll
    for (int j = 0; j < 4; j++)
        tile[threadIdx.y + j * 8][threadIdx.x] =
            src[(size_t)(by + threadIdx.y + j * 8) * 512 + bx + threadIdx.x];
    __syncthreads();
    #pragma unroll
    for (int j = 0; j < 4; j++)
        dst[(size_t)(bx + threadIdx.y + j * 8) * 512 + by + threadIdx.x] =
            tile[threadIdx.x][threadIdx.y + j * 8];
}
__global__ void k_tohalf(const float4* __restrict__ src, uint2* __restrict__ dst, int n4) {
    int i = blockIdx.x * blockDim.x + threadIdx.x;
    if (i < n4) {
        float4 v = src[i];
        uint2 o;
        o.x = pack2(v.x, v.y);
        o.y = pack2(v.z, v.w);
        dst[i] = o;
    }
}

// BN + ELU; HOUT: write half, else fp32.
template<bool HOUT>
__global__ void __launch_bounds__(256) k_bn_elu(const float4* __restrict__ X,
                                                void* __restrict__ Y,
                                                const float4* __restrict__ sum4,
                                                const float4* __restrict__ sumsq4,
                                                const float4* __restrict__ g4,
                                                const float4* __restrict__ bt4) {
    const float invN = 1.f / (float)RR;
    const int total4 = RR * Ee / 4;
    for (int i = blockIdx.x * blockDim.x + threadIdx.x; i < total4;
         i += gridDim.x * blockDim.x) {
        const int c4 = i & 127;
        float4 sm = sum4[c4], sq = sumsq4[c4], gg = g4[c4], bb = bt4[c4];
        float4 v = X[i];
        float m, va, sc, y;
        float4 o;
        m = sm.x * invN; va = sq.x * invN - m * m; sc = gg.x * rsqrtf(va + EPSV);
        y = (v.x - m) * sc + bb.x; o.x = y > 0.f ? y : expm1f(y);
        m = sm.y * invN; va = sq.y * invN - m * m; sc = gg.y * rsqrtf(va + EPSV);
        y = (v.y - m) * sc + bb.y; o.y = y > 0.f ? y : expm1f(y);
        m = sm.z * invN; va = sq.z * invN - m * m; sc = gg.z * rsqrtf(va + EPSV);
        y = (v.z - m) * sc + bb.z; o.z = y > 0.f ? y : expm1f(y);
        m = sm.w * invN; va = sq.w * invN - m * m; sc = gg.w * rsqrtf(va + EPSV);
        y = (v.w - m) * sc + bb.w; o.w = y > 0.f ? y : expm1f(y);
        if (HOUT) {
            uint2 u;
            u.x = pack2(o.x, o.y);
            u.y = pack2(o.z, o.w);
            ((uint2*)Y)[i] = u;
        } else {
            ((float4*)Y)[i] = o;
        }
    }
}

// BN4 + softmax over q; reads fp32 wT rows, writes half.
__global__ void k_bn_softmax(const float* __restrict__ Wt, __half* __restrict__ Wh,
                             const float* __restrict__ sum, const float* __restrict__ sumsq,
                             const float* __restrict__ g4, const float* __restrict__ b4) {
    const int bk = blockIdx.x;
    const int k = bk & 511;
    const float* row = Wt + ((size_t)bk << 9);
    const float invN = 1.f / (float)RR;
    const float mean = sum[k] * invN;
    const float var = sumsq[k] * invN - mean * mean;
    const float sc = g4[k] * rsqrtf(var + EPSV);
    const float shf = b4[k] - mean * sc;
    const int t = threadIdx.x;
    float2 xv = *(const float2*)(row + 2 * t);
    float x0 = xv.x * sc + shf;
    float x1 = xv.y * sc + shf;
    __shared__ float sh[32];
    float mx = blockReduceMax(fmaxf(x0, x1), sh);
    float e0 = expf(x0 - mx), e1 = expf(x1 - mx);
    float tot = blockReduceSum(e0 + e1, sh);
    float inv = 1.f / tot;
    *(uint32_t*)(Wh + ((size_t)bk << 9) + 2 * t) = pack2(e0 * inv, e1 * inv);
}

// ---------------------------------------------------------------------------
// fp16 GEMMs: 128x128 C tile, BK=32, 128 threads (4 warps 2x2), 64x64 warp
// tiles, register double-buffered smem, one sync/iter, stats fused.
// ---------------------------------------------------------------------------

// GEMM1: C = unfold(m1 fp32) @ fh + kb. A gathered fp32, cvt at staging. Col stats.
__global__ void __launch_bounds__(128) k_gemm1(const float* __restrict__ Am,
                                               const __half* __restrict__ Bh,
                                               const float* __restrict__ kb,
                                               float* __restrict__ C,
                                               float* __restrict__ ssum,
                                               float* __restrict__ ssq) {
    __shared__ uint32_t As[2][16][PADW];
    __shared__ uint32_t Bs[2][16][PADW];
    float c[4][8][4] = {{{0.f}}};
    const int tid = threadIdx.x;
    const int lane = tid & 31, wid = tid >> 5;
    const int g = lane >> 2, t = lane & 3;
    const int wm = (wid & 1) << 6, wn = (wid >> 1) << 6;
    const int br = blockIdx.y << 7, bc = blockIdx.x << 7;
    const int kpb = tid >> 5, c0 = (tid & 31) << 2;

    const int row = br + tid;
    const int bA = row >> 9, lA = row & 511;

    float4 av[8];
    uint2 bx[4], by[4];
    {
        const int sl = lA - 2;
        if ((unsigned)sl < 512u)
            ld_mmajf(av, Am + (((size_t)(bA << 9) + sl) << 9));
        else
            #pragma unroll
            for (int j = 0; j < 8; j++) av[j] = make_float4(0.f, 0.f, 0.f, 0.f);
        ld_kmaj(bx, by, Bh, Ee, 0, kpb, bc + c0);
    }
    st_mmajf(As[0], tid, av);
    st_kmaj(Bs[0], kpb, c0, bx, by);

    const int nIter = KE / 32;
    for (int i = 0; i < nIter; i++) {
        const int buf = i & 1, nb = buf ^ 1;
        __syncthreads();
        const int k1 = (i + 1) << 5;
        if (i + 1 < nIter) {
            const int sl = lA + (k1 >> 9) - 2;
            if ((unsigned)sl < 512u)
                ld_mmajf(av, Am + (((size_t)(bA << 9) + sl) << 9) + (k1 & 511));
            else
                #pragma unroll
                for (int j = 0; j < 8; j++) av[j] = make_float4(0.f, 0.f, 0.f, 0.f);
            ld_kmaj(bx, by, Bh, Ee, k1, kpb, bc + c0);
        }
        mma_core64h(As[buf], Bs[buf], c, g, t, wm, wn);
        if (i + 1 < nIter) {
            st_mmajf(As[nb], tid, av);
            st_kmaj(Bs[nb], kpb, c0, bx, by);
        }
    }

    float cs[16] = {0.f}, cq[16] = {0.f};
    #pragma unroll
    for (int mt = 0; mt < 4; mt++)
        #pragma unroll
        for (int i = 0; i < 2; i++) {
            const int rowo = br + wm + mt * 16 + g + 8 * i;
            const int l = rowo & 511;
            #pragma unroll
            for (int nt = 0; nt < 8; nt++) {
                const int col = bc + wn + nt * 8 + 2 * t;
                float2 bvv = *(const float2*)(kb + (size_t)l * 512 + col);
                float2 v;
                v.x = c[mt][nt][2 * i + 0] + bvv.x;
                v.y = c[mt][nt][2 * i + 1] + bvv.y;
                cs[nt * 2 + 0] += v.x; cq[nt * 2 + 0] += v.x * v.x;
                cs[nt * 2 + 1] += v.y; cq[nt * 2 + 1] += v.y * v.y;
                *(float2*)(C + (size_t)rowo * 512 + col) = v;
            }
        }
    colstats_epilogue(ssum, ssq, cs, cq, g, t, bc + wn);
}

// Fused NN GEMMs (z=0: q2 = l@wq + qb ; z=1: k2 = l@wk + kb). Col stats fused.
__global__ void __launch_bounds__(128) k_gemm_nn(const __half* __restrict__ Ah,
                                                 const __half* __restrict__ Bqh,
                                                 const __half* __restrict__ Bkh,
                                                 const float* __restrict__ biasq,
                                                 const float* __restrict__ biask,
                                                 float* __restrict__ Cq,
                                                 float* __restrict__ Ck,
                                                 float* __restrict__ stats) {
    const __half* Bh = blockIdx.z ? Bkh : Bqh;
    const float* bias = blockIdx.z ? biask : biasq;
    float* C = blockIdx.z ? Ck : Cq;
    float* ssum = stats + (blockIdx.z ? 4 * Ee : 2 * Ee);
    float* ssq = ssum + Ee;
    __shared__ uint32_t As[2][16][PADW];
    __shared__ uint32_t Bs[2][16][PADW];
    float c[4][8][4] = {{{0.f}}};
    const int tid = threadIdx.x;
    const int lane = tid & 31, wid = tid >> 5;
    const int g = lane >> 2, t = lane & 3;
    const int wm = (wid & 1) << 6, wn = (wid >> 1) << 6;
    const int br = blockIdx.y << 7, bc = blockIdx.x << 7;
    const int kpb = tid >> 5, c0 = (tid & 31) << 2;

    uint4 av[4];
    uint2 bx[4], by[4];
    ld_mmaj(av, Ah + (size_t)(br + tid) * 512);
    ld_kmaj(bx, by, Bh, 512, 0, kpb, bc + c0);
    st_mmaj(As[0], tid, av);
    st_kmaj(Bs[0], kpb, c0, bx, by);

    const int nIter = 16;
    for (int i = 0; i < nIter; i++) {
        const int buf = i & 1, nb = buf ^ 1;
        __syncthreads();
        const int k1 = (i + 1) << 5;
        if (i + 1 < nIter) {
            ld_mmaj(av, Ah + (size_t)(br + tid) * 512 + k1);
            ld_kmaj(bx, by, Bh, 512, k1, kpb, bc + c0);
        }
        mma_core64h(As[buf], Bs[buf], c, g, t, wm, wn);
        if (i + 1 < nIter) {
            st_mmaj(As[nb], tid, av);
            st_kmaj(Bs[nb], kpb, c0, bx, by);
        }
    }

    float cs[16] = {0.f}, cq[16] = {0.f};
    #pragma unroll
    for (int mt = 0; mt < 4; mt++)
        #pragma unroll
        for (int i = 0; i < 2; i++) {
            const int rowo = br + wm + mt * 16 + g + 8 * i;
            const int l = rowo & 511;
            #pragma unroll
            for (int nt = 0; nt < 8; nt++) {
                const int col = bc + wn + nt * 8 + 2 * t;
                float2 bvv = *(const float2*)(bias + (size_t)l * 512 + col);
                float2 v;
                v.x = c[mt][nt][2 * i + 0] + bvv.x;
                v.y = c[mt][nt][2 * i + 1] + bvv.y;
                cs[nt * 2 + 0] += v.x; cq[nt * 2 + 0] += v.x * v.x;
                cs[nt * 2 + 1] += v.y; cq[nt * 2 + 1] += v.y * v.y;
                *(float2*)(C + (size_t)rowo * 512 + col) = v;
            }
        }
    colstats_epilogue(ssum, ssq, cs, cq, g, t, bc + wn);
}

// Batched NT: C[k,q] = sum_e k2[k,e]*q2[q,e] + wbT. Both m-major. Row stats.
__global__ void __launch_bounds__(128) k_gemm_nt(const __half* __restrict__ Ain,
                                                 const __half* __restrict__ Bin,
                                                 const float* __restrict__ wbT,
                                                 float* __restrict__ Cout,
                                                 float* __restrict__ rsum,
                                                 float* __restrict__ rsq) {
    const int bz = blockIdx.z;
    const __half* A = Ain + (size_t)bz * Ll * Ee;
    const __half* Bm = Bin + (size_t)bz * Ll * Ee;
    float* C = Cout + (size_t)bz * Ll * Ll;
    __shared__ uint32_t As[2][16][PADW];
    __shared__ uint32_t Bs[2][16][PADW];
    float c[4][8][4] = {{{0.f}}};
    const int tid = threadIdx.x;
    const int lane = tid & 31, wid = tid >> 5;
    const int g = lane >> 2, t = lane & 3;
    const int wm = (wid & 1) << 6, wn = (wid >> 1) << 6;
    const int br = blockIdx.y << 7, bc = blockIdx.x << 7;

    uint4 av[4], bv[4];
    ld_mmaj(av, A + (size_t)(br + tid) * 512);
    ld_mmaj(bv, Bm + (size_t)(bc + tid) * 512);
    st_mmaj(As[0], tid, av);
    st_mmaj(Bs[0], tid, bv);

    const int nIter = 16;
    for (int i = 0; i < nIter; i++) {
        const int buf = i & 1, nb = buf ^ 1;
        __syncthreads();
        const int k1 = (i + 1) << 5;
        if (i + 1 < nIter) {
            ld_mmaj(av, A + (size_t)(br + tid) * 512 + k1);
            ld_mmaj(bv, Bm + (size_t)(bc + tid) * 512 + k1);
        }
        mma_core64h(As[buf], Bs[buf], c, g, t, wm, wn);
        if (i + 1 < nIter) {
            st_mmaj(As[nb], tid, av);
            st_mmaj(Bs[nb], tid, bv);
        }
    }

    float rs[8] = {0.f}, rq[8] = {0.f};
    #pragma unroll
    for (int mt = 0; mt < 4; mt++)
        #pragma unroll
        for (int i = 0; i < 2; i++) {
            const int rowo = br + wm + mt * 16 + g + 8 * i;
            #pragma unroll
            for (int nt = 0; nt < 8; nt++) {
                const int col = bc + wn + nt * 8 + 2 * t;
                float2 bv2 = *(const float2*)(wbT + (size_t)rowo * 512 + col);
                float2 v;
                v.x = c[mt][nt][2 * i + 0] + bv2.x;
                v.y = c[mt][nt][2 * i + 1] + bv2.y;
                rs[mt * 2 + i] += v.x + v.y;
                rq[mt * 2 + i] += v.x * v.x + v.y * v.y;
                *(float2*)(C + (size_t)rowo * 512 + col) = v;
            }
        }
    #pragma unroll
    for (int x = 0; x < 8; x++) {
        float s = rs[x], q = rq[x];
        s += __shfl_xor_sync(0xffffffffu, s, 1); q += __shfl_xor_sync(0xffffffffu, q, 1);
        s += __shfl_xor_sync(0xffffffffu, s, 2); q += __shfl_xor_sync(0xffffffffu, q, 2);
        if (t == 0) {
            const int rowo = br + wm + (x >> 1) * 16 + g + 8 * (x & 1);
            atomicAdd(&rsum[rowo], s);
            atomicAdd(&rsq[rowo], q);
        }
    }
}

// Batched TN: C[q,e] = sum_k wh[k,q]*lh[k,e]. Both k-major. Col stats fused.
__global__ void __launch_bounds__(128) k_gemm_tn(const __half* __restrict__ Ain,
                                                 const __half* __restrict__ Bin,
                                                 float* __restrict__ Cout,
                                                 float* __restrict__ ssum,
                                                 float* __restrict__ ssq) {
    const int bz = blockIdx.z;
    const __half* A = Ain + (size_t)bz * Ll * Ll;
    const __half* Bm = Bin + (size_t)bz * Ll * Ee;
    float* C = Cout + (size_t)bz * Ll * Ee;
    __shared__ uint32_t As[2][16][PADW];
    __shared__ uint32_t Bs[2][16][PADW];
    float c[4][8][4] = {{{0.f}}};
    const int tid = threadIdx.x;
    const int lane = tid & 31, wid = tid >> 5;
    const int g = lane >> 2, t = lane & 3;
    const int wm = (wid & 1) << 6, wn = (wid >> 1) << 6;
    const int br = blockIdx.y << 7, bc = blockIdx.x << 7;
    const int kpb = tid >> 5, c0 = (tid & 31) << 2;

    uint2 ax[4], ay[4], bx[4], by[4];
    ld_kmaj(ax, ay, A, 512, 0, kpb, br + c0);
    ld_kmaj(bx, by, Bm, 512, 0, kpb, bc + c0);
    st_kmaj(As[0], kpb, c0, ax, ay);
    st_kmaj(Bs[0], kpb, c0, bx, by);

    const int nIter = 16;
    for (int i = 0; i < nIter; i++) {
        const int buf = i & 1, nb = buf ^ 1;
        __syncthreads();
        const int k1 = (i + 1) << 5;
        if (i + 1 < nIter) {
            ld_kmaj(ax, ay, A, 512, k1, kpb, br + c0);
            ld_kmaj(bx, by, Bm, 512, k1, kpb, bc + c0);
        }
        mma_core64h(As[buf], Bs[buf], c, g, t, wm, wn);
        if (i + 1 < nIter) {
            st_kmaj(As[nb], kpb, c0, ax, ay);
            st_kmaj(Bs[nb], kpb, c0, bx, by);
        }
    }

    float cs[16] = {0.f}, cq[16] = {0.f};
    #pragma unroll
    for (int mt = 0; mt < 4; mt++)
        #pragma unroll
        for (int i = 0; i < 2; i++) {
            const int rowo = br + wm + mt * 16 + g + 8 * i;
            #pragma unroll
            for (int nt = 0; nt < 8; nt++) {
                const int col = bc + wn + nt * 8 + 2 * t;
                float2 v;
                v.x = c[mt][nt][2 * i + 0];
                v.y = c[mt][nt][2 * i + 1];
                cs[nt * 2 + 0] += v.x; cq[nt * 2 + 0] += v.x * v.x;
                cs[nt * 2 + 1] += v.y; cq[nt * 2 + 1] += v.y * v.y;
                *(float2*)(C + (size_t)rowo * 512 + col) = v;
            }
        }
    colstats_epilogue(ssum, ssq, cs, cq, g, t, bc + wn);
}

extern "C" void kernel_launch(void* const* d_in, const int* in_sizes, int n_in,
                              void* d_out, int out_size) {
    const float* m1 = (const float*)d_in[0];
    const float* f  = (const float*)d_in[1];
    const float* wq = (const float*)d_in[2];
    const float* wk = (const float*)d_in[3];
    const float* qb = (const float*)d_in[4];
    const float* kb = (const float*)d_in[5];
    const float* wb = (const float*)d_in[6];
    const float* g1 = (const float*)d_in[7];  const float* b1 = (const float*)d_in[8];
    const float* g2 = (const float*)d_in[9];  const float* b2 = (const float*)d_in[10];
    const float* g3 = (const float*)d_in[11]; const float* b3 = (const float*)d_in[12];
    const float* g4 = (const float*)d_in[13]; const float* b4 = (const float*)d_in[14];
    const float* g5 = (const float*)d_in[15]; const float* b5 = (const float*)d_in[16];

    float *pl, *pq, *pk, *pw, *po, *ps, *pwbT;
    __half *pfh, *pwqh, *pwkh, *plh, *pqh, *pkh, *pwh;
    cudaGetSymbolAddress((void**)&pl, g_l);
    cudaGetSymbolAddress((void**)&pq, g_q);
    cudaGetSymbolAddress((void**)&pk, g_k);
    cudaGetSymbolAddress((void**)&pw, g_w);
    cudaGetSymbolAddress((void**)&po, g_o);
    cudaGetSymbolAddress((void**)&ps, g_s);
    cudaGetSymbolAddress((void**)&pwbT, g_wbT);
    cudaGetSymbolAddress((void**)&pfh, g_fh);
    cudaGetSymbolAddress((void**)&pwqh, g_wqh);
    cudaGetSymbolAddress((void**)&pwkh, g_wkh);
    cudaGetSymbolAddress((void**)&plh, g_lh);
    cudaGetSymbolAddress((void**)&pqh, g_qh);
    cudaGetSymbolAddress((void**)&pkh, g_kh);
    cudaGetSymbolAddress((void**)&pwh, g_wh);

    const int T = 256, TG = 128;

    k_zero<<<20, T>>>(ps, 10 * Ee);
    k_transpose<<<dim3(16, 16), dim3(32, 8)>>>(wb, pwbT);
    k_tohalf<<<1280, T>>>((const float4*)f, (uint2*)pfh, KE * Ee / 4);
    k_tohalf<<<256, T>>>((const float4*)wq, (uint2*)pwqh, Ee * Ee / 4);
    k_tohalf<<<256, T>>>((const float4*)wk, (uint2*)pwkh, Ee * Ee / 4);

    // 1) l_pre = unfold(m1) @ f + kb (A cvt at staging) ; BN1+ELU -> half
    k_gemm1<<<dim3(4, 128), TG>>>(m1, pfh, kb, pl, ps + 0 * Ee, ps + 1 * Ee);
    k_bn_elu<true><<<2048, T>>>((const float4*)pl, plh,
                                (const float4*)(ps + 0 * Ee), (const float4*)(ps + 1 * Ee),
                                (const float4*)g1, (const float4*)b1);

    // 2) q2 / k2 ; BN+ELU -> half
    k_gemm_nn<<<dim3(4, 128, 2), TG>>>(plh, pwqh, pwkh, qb, kb, pq, pk, ps);
    k_bn_elu<true><<<2048, T>>>((const float4*)pq, pqh,
                                (const float4*)(ps + 2 * Ee), (const float4*)(ps + 3 * Ee),
                                (const float4*)g2, (const float4*)b2);
    k_bn_elu<true><<<2048, T>>>((const float4*)pk, pkh,
                                (const float4*)(ps + 4 * Ee), (const float4*)(ps + 5 * Ee),
                                (const float4*)g3, (const float4*)b3);

    // 3) wT = k2 @ q2^T + wbT ; BN4 + softmax -> half
    k_gemm_nt<<<dim3(4, 4, 32), TG>>>(pkh, pqh, pwbT, pw, ps + 8 * Ee, ps + 9 * Ee);
    k_bn_softmax<<<16384, T>>>(pw, pwh, ps + 8 * Ee, ps + 9 * Ee, g4, b4);

    // 4) out = wT^T @ l ; BN5 + ELU -> d_out (fp32)
    k_gemm_tn<<<dim3(4, 4, 32), TG>>>(pwh, plh, po, ps + 6 * Ee, ps + 7 * Ee);
    k_bn_elu<false><<<2048, T>>>((const float4*)po, d_out,
                                 (const float4*)(ps + 6 * Ee), (const float4*)(ps + 7 * Ee),
                                 (const float4*)g5, (const float4*)b5);
}

// round 13
// speedup vs baseline: 1.1492x; 1.1492x over previous
#include <cuda_runtime.h>
#include <cuda_fp16.h>
#include <math.h>
#include <stdint.h>

#define Bb 32
#define Ll 512
#define Ee 512
#define RR (Bb*Ll)
#define KE (5*Ee)
#define EPSV 1e-3f
#define PADW 136

// fp32 scratch (pre-BN activations for exact stats)
__device__ float g_l[RR*Ee];
__device__ float g_q[RR*Ee];
__device__ float g_k[RR*Ee];
__device__ float g_w[Bb*Ll*Ll];     // wT[b,k,q] pre-BN fp32
__device__ float g_o[RR*Ee];
__device__ float g_wbT[Ll*Ll];
__device__ float g_s[10*Ee];
// fp16 operands
__device__ __half g_m1h[RR*Ee];
__device__ __half g_fh[KE*Ee];
__device__ __half g_wqh[Ee*Ee];
__device__ __half g_wkh[Ee*Ee];
__device__ __half g_lh[RR*Ee];
__device__ __half g_qh[RR*Ee];
__device__ __half g_kh[RR*Ee];
__device__ __half g_wh[Bb*Ll*Ll];

__device__ __forceinline__ uint32_t pack2(float a, float b) {
    __half2 h = __floats2half2_rn(a, b);
    return *(uint32_t*)&h;
}

// ---------------------------------------------------------------------------
// fp16 mma core: 64x64 warp tile over [16][PADW] kpair-word tiles, BK=32.
// ---------------------------------------------------------------------------
__device__ __forceinline__ void mma_core64h(const uint32_t (*As)[PADW],
                                            const uint32_t (*Bs)[PADW],
                                            float c[4][8][4],
                                            int g, int t, int wm, int wn) {
    #pragma unroll
    for (int ks = 0; ks < 2; ks++) {
        const int kb = ks * 8;
        uint32_t a[4][4], b[8][2];
        #pragma unroll
        for (int mt = 0; mt < 4; mt++) {
            const int m = wm + mt * 16 + g;
            a[mt][0] = As[kb + t][m];
            a[mt][1] = As[kb + t][m + 8];
            a[mt][2] = As[kb + t + 4][m];
            a[mt][3] = As[kb + t + 4][m + 8];
        }
        #pragma unroll
        for (int nt = 0; nt < 8; nt++) {
            const int n = wn + nt * 8 + g;
            b[nt][0] = Bs[kb + t][n];
            b[nt][1] = Bs[kb + t + 4][n];
        }
        #pragma unroll
        for (int mt = 0; mt < 4; mt++)
            #pragma unroll
            for (int nt = 0; nt < 8; nt++)
                asm volatile(
                    "mma.sync.aligned.m16n8k16.row.col.f32.f16.f16.f32 "
                    "{%0,%1,%2,%3},{%4,%5,%6,%7},{%8,%9},{%0,%1,%2,%3};"
                    : "+f"(c[mt][nt][0]), "+f"(c[mt][nt][1]),
                      "+f"(c[mt][nt][2]), "+f"(c[mt][nt][3])
                    : "r"(a[mt][0]), "r"(a[mt][1]), "r"(a[mt][2]), "r"(a[mt][3]),
                      "r"(b[nt][0]), "r"(b[nt][1]));
    }
}

// m-major staging: thread col m = tid, 32 k-contig halves = 4 x uint4.
__device__ __forceinline__ void ld_mmaj(uint4 v[4], const __half* src) {
    const uint4* p = (const uint4*)src;
    v[0] = p[0]; v[1] = p[1]; v[2] = p[2]; v[3] = p[3];
}
__device__ __forceinline__ void st_mmaj(uint32_t (*S)[PADW], int m, const uint4 v[4]) {
    #pragma unroll
    for (int u = 0; u < 4; u++) {
        S[4*u + 0][m] = v[u].x;
        S[4*u + 1][m] = v[u].y;
        S[4*u + 2][m] = v[u].z;
        S[4*u + 3][m] = v[u].w;
    }
}
// k-major staging: thread covers colquad c0 = 4*(tid&31), kp = (tid>>5)+4j.
__device__ __forceinline__ void ld_kmaj(uint2 x[4], uint2 y[4], const __half* B,
                                        int ld, int k0, int kpb, int gcol) {
    #pragma unroll
    for (int j = 0; j < 4; j++) {
        const __half* r = B + (size_t)(k0 + 2 * (kpb + 4 * j)) * ld + gcol;
        x[j] = *(const uint2*)r;
        y[j] = *(const uint2*)(r + ld);
    }
}
__device__ __forceinline__ void st_kmaj(uint32_t (*S)[PADW], int kpb, int c0,
                                        const uint2 x[4], const uint2 y[4]) {
    #pragma unroll
    for (int j = 0; j < 4; j++) {
        const int kp = kpb + 4 * j;
        uint4 w;
        w.x = __byte_perm(x[j].x, y[j].x, 0x5410);
        w.y = __byte_perm(x[j].x, y[j].x, 0x7632);
        w.z = __byte_perm(x[j].y, y[j].y, 0x5410);
        w.w = __byte_perm(x[j].y, y[j].y, 0x7632);
        *(uint4*)&S[kp][c0] = w;
    }
}

__device__ __forceinline__ void colstats_epilogue(float* __restrict__ sum,
                                                  float* __restrict__ sumsq,
                                                  const float cs[16], const float cq[16],
                                                  int g, int t, int bcwn) {
    #pragma unroll
    for (int x = 0; x < 16; x++) {
        float s = cs[x], q = cq[x];
        s += __shfl_xor_sync(0xffffffffu, s, 4);  q += __shfl_xor_sync(0xffffffffu, q, 4);
        s += __shfl_xor_sync(0xffffffffu, s, 8);  q += __shfl_xor_sync(0xffffffffu, q, 8);
        s += __shfl_xor_sync(0xffffffffu, s, 16); q += __shfl_xor_sync(0xffffffffu, q, 16);
        if (g == 0) {
            const int col = bcwn + (x >> 1) * 8 + 2 * t + (x & 1);
            atomicAdd(&sum[col], s);
            atomicAdd(&sumsq[col], q);
        }
    }
}
__device__ __forceinline__ float blockReduceSum(float v, float* sh) {
    const int t = threadIdx.x;
    #pragma unroll
    for (int o = 16; o > 0; o >>= 1) v += __shfl_xor_sync(0xffffffffu, v, o);
    if ((t & 31) == 0) sh[t >> 5] = v;
    __syncthreads();
    if (t < 32) {
        v = (t < (int)(blockDim.x >> 5)) ? sh[t] : 0.f;
        #pragma unroll
        for (int o = 16; o > 0; o >>= 1) v += __shfl_xor_sync(0xffffffffu, v, o);
        if (t == 0) sh[0] = v;
    }
    __syncthreads();
    float r = sh[0];
    __syncthreads();
    return r;
}
__device__ __forceinline__ float blockReduceMax(float v, float* sh) {
    const int t = threadIdx.x;
    #pragma unroll
    for (int o = 16; o > 0; o >>= 1) v = fmaxf(v, __shfl_xor_sync(0xffffffffu, v, o));
    if ((t & 31) == 0) sh[t >> 5] = v;
    __syncthreads();
    if (t < 32) {
        v = (t < (int)(blockDim.x >> 5)) ? sh[t] : -INFINITY;
        #pragma unroll
        for (int o = 16; o > 0; o >>= 1) v = fmaxf(v, __shfl_xor_sync(0xffffffffu, v, o));
        if (t == 0) sh[0] = v;
    }
    __syncthreads();
    float r = sh[0];
    __syncthreads();
    return r;
}

// Fused pre-pass: zero stats + fp32->fp16 for m1 / f / wq / wk (region split).
#define N_M1 (RR*Ee/4)
#define N_F  (KE*Ee/4)
#define N_W  (Ee*Ee/4)
#define N_PREP (N_M1 + N_F + 2*N_W)
__global__ void __launch_bounds__(256) k_prep(const float4* __restrict__ m1,
                                              uint2* __restrict__ m1h,
                                              const float4* __restrict__ f,
                                              uint2* __restrict__ fh,
                                              const float4* __restrict__ wq,
                                              uint2* __restrict__ wqh,
                                              const float4* __restrict__ wk,
                                              uint2* __restrict__ wkh,
                                              float4* __restrict__ ps4) {
    const int i = blockIdx.x * 256 + threadIdx.x;
    if (i < 10 * Ee / 4) ps4[i] = make_float4(0.f, 0.f, 0.f, 0.f);
    const float4* src;
    uint2* dst;
    int j = i;
    if (j < N_M1) { src = m1; dst = m1h; }
    else {
        j -= N_M1;
        if (j < N_F) { src = f; dst = fh; }
        else {
            j -= N_F;
            if (j < N_W) { src = wq; dst = wqh; }
            else { j -= N_W; if (j >= N_W) return; src = wk; dst = wkh; }
        }
    }
    float4 v = src[j];
    uint2 o;
    o.x = pack2(v.x, v.y);
    o.y = pack2(v.z, v.w);
    dst[j] = o;
}

__global__ void k_transpose(const float* __restrict__ src, float* __restrict__ dst) {
    __shared__ float tile[32][33];
    const int bx = blockIdx.x << 5, by = blockIdx.y << 5;
    #pragma unroll
    for (int j = 0; j < 4; j++)
        tile[threadIdx.y + j * 8][threadIdx.x] =
            src[(size_t)(by + threadIdx.y + j * 8) * 512 + bx + threadIdx.x];
    __syncthreads();
    #pragma unroll
    for (int j = 0; j < 4; j++)
        dst[(size_t)(bx + threadIdx.y + j * 8) * 512 + by + threadIdx.x] =
            tile[threadIdx.x][threadIdx.y + j * 8];
}

// BN + ELU; HOUT: write half, else fp32.
template<bool HOUT>
__global__ void __launch_bounds__(256) k_bn_elu(const float4* __restrict__ X,
                                                void* __restrict__ Y,
                                                const float4* __restrict__ sum4,
                                                const float4* __restrict__ sumsq4,
                                                const float4* __restrict__ g4,
                                                const float4* __restrict__ bt4) {
    const float invN = 1.f / (float)RR;
    const int total4 = RR * Ee / 4;
    for (int i = blockIdx.x * blockDim.x + threadIdx.x; i < total4;
         i += gridDim.x * blockDim.x) {
        const int c4 = i & 127;
        float4 sm = sum4[c4], sq = sumsq4[c4], gg = g4[c4], bb = bt4[c4];
        float4 v = X[i];
        float m, va, sc, y;
        float4 o;
        m = sm.x * invN; va = sq.x * invN - m * m; sc = gg.x * rsqrtf(va + EPSV);
        y = (v.x - m) * sc + bb.x; o.x = y > 0.f ? y : expm1f(y);
        m = sm.y * invN; va = sq.y * invN - m * m; sc = gg.y * rsqrtf(va + EPSV);
        y = (v.y - m) * sc + bb.y; o.y = y > 0.f ? y : expm1f(y);
        m = sm.z * invN; va = sq.z * invN - m * m; sc = gg.z * rsqrtf(va + EPSV);
        y = (v.z - m) * sc + bb.z; o.z = y > 0.f ? y : expm1f(y);
        m = sm.w * invN; va = sq.w * invN - m * m; sc = gg.w * rsqrtf(va + EPSV);
        y = (v.w - m) * sc + bb.w; o.w = y > 0.f ? y : expm1f(y);
        if (HOUT) {
            uint2 u;
            u.x = pack2(o.x, o.y);
            u.y = pack2(o.z, o.w);
            ((uint2*)Y)[i] = u;
        } else {
            ((float4*)Y)[i] = o;
        }
    }
}

// Merged BN+ELU for q (y=0) and k (y=1); half output.
__global__ void __launch_bounds__(256) k_bn_elu_qk(const float4* __restrict__ Xq,
                                                   uint2* __restrict__ Yq,
                                                   const float4* __restrict__ Xk,
                                                   uint2* __restrict__ Yk,
                                                   const float* __restrict__ stats,
                                                   const float4* __restrict__ gq,
                                                   const float4* __restrict__ bq,
                                                   const float4* __restrict__ gk,
                                                   const float4* __restrict__ bk) {
    const int z = blockIdx.y;
    const float4* X = z ? Xk : Xq;
    uint2* Y = z ? Yk : Yq;
    const float4* sum4 = (const float4*)(stats + (z ? 4 * Ee : 2 * Ee));
    const float4* sumsq4 = (const float4*)(stats + (z ? 5 * Ee : 3 * Ee));
    const float4* g4 = z ? gk : gq;
    const float4* bt4 = z ? bk : bq;
    const float invN = 1.f / (float)RR;
    const int total4 = RR * Ee / 4;
    for (int i = blockIdx.x * blockDim.x + threadIdx.x; i < total4;
         i += gridDim.x * blockDim.x) {
        const int c4 = i & 127;
        float4 sm = sum4[c4], sq = sumsq4[c4], gg = g4[c4], bb = bt4[c4];
        float4 v = X[i];
        float m, va, sc, y;
        float4 o;
        m = sm.x * invN; va = sq.x * invN - m * m; sc = gg.x * rsqrtf(va + EPSV);
        y = (v.x - m) * sc + bb.x; o.x = y > 0.f ? y : expm1f(y);
        m = sm.y * invN; va = sq.y * invN - m * m; sc = gg.y * rsqrtf(va + EPSV);
        y = (v.y - m) * sc + bb.y; o.y = y > 0.f ? y : expm1f(y);
        m = sm.z * invN; va = sq.z * invN - m * m; sc = gg.z * rsqrtf(va + EPSV);
        y = (v.z - m) * sc + bb.z; o.z = y > 0.f ? y : expm1f(y);
        m = sm.w * invN; va = sq.w * invN - m * m; sc = gg.w * rsqrtf(va + EPSV);
        y = (v.w - m) * sc + bb.w; o.w = y > 0.f ? y : expm1f(y);
        uint2 u;
        u.x = pack2(o.x, o.y);
        u.y = pack2(o.z, o.w);
        Y[i] = u;
    }
}

// BN4 + softmax over q; reads fp32 wT rows, writes half.
__global__ void k_bn_softmax(const float* __restrict__ Wt, __half* __restrict__ Wh,
                             const float* __restrict__ sum, const float* __restrict__ sumsq,
                             const float* __restrict__ g4, const float* __restrict__ b4) {
    const int bk = blockIdx.x;
    const int k = bk & 511;
    const float* row = Wt + ((size_t)bk << 9);
    const float invN = 1.f / (float)RR;
    const float mean = sum[k] * invN;
    const float var = sumsq[k] * invN - mean * mean;
    const float sc = g4[k] * rsqrtf(var + EPSV);
    const float shf = b4[k] - mean * sc;
    const int t = threadIdx.x;
    float2 xv = *(const float2*)(row + 2 * t);
    float x0 = xv.x * sc + shf;
    float x1 = xv.y * sc + shf;
    __shared__ float sh[32];
    float mx = blockReduceMax(fmaxf(x0, x1), sh);
    float e0 = expf(x0 - mx), e1 = expf(x1 - mx);
    float tot = blockReduceSum(e0 + e1, sh);
    float inv = 1.f / tot;
    *(uint32_t*)(Wh + ((size_t)bk << 9) + 2 * t) = pack2(e0 * inv, e1 * inv);
}

// ---------------------------------------------------------------------------
// fp16 GEMMs (identical to R10 passing code)
// ---------------------------------------------------------------------------

// GEMM1: C = unfold(m1h) @ fh + kb. A gathered m-major, B k-major. Col stats.
__global__ void __launch_bounds__(128) k_gemm1(const __half* __restrict__ Ah,
                                               const __half* __restrict__ Bh,
                                               const float* __restrict__ kb,
                                               float* __restrict__ C,
                                               float* __restrict__ ssum,
                                               float* __restrict__ ssq) {
    __shared__ uint32_t As[2][16][PADW];
    __shared__ uint32_t Bs[2][16][PADW];
    float c[4][8][4] = {{{0.f}}};
    const int tid = threadIdx.x;
    const int lane = tid & 31, wid = tid >> 5;
    const int g = lane >> 2, t = lane & 3;
    const int wm = (wid & 1) << 6, wn = (wid >> 1) << 6;
    const int br = blockIdx.y << 7, bc = blockIdx.x << 7;
    const int kpb = tid >> 5, c0 = (tid & 31) << 2;

    const int row = br + tid;
    const int bA = row >> 9, lA = row & 511;

    uint4 av[4];
    uint2 bx[4], by[4];
    {
        const int sl = lA - 2;
        if ((unsigned)sl < 512u)
            ld_mmaj(av, Ah + (((size_t)(bA << 9) + sl) << 9));
        else
            av[0] = av[1] = av[2] = av[3] = make_uint4(0, 0, 0, 0);
        ld_kmaj(bx, by, Bh, Ee, 0, kpb, bc + c0);
    }
    st_mmaj(As[0], tid, av);
    st_kmaj(Bs[0], kpb, c0, bx, by);

    const int nIter = KE / 32;
    for (int i = 0; i < nIter; i++) {
        const int buf = i & 1, nb = buf ^ 1;
        __syncthreads();
        const int k1 = (i + 1) << 5;
        if (i + 1 < nIter) {
            const int sl = lA + (k1 >> 9) - 2;
            if ((unsigned)sl < 512u)
                ld_mmaj(av, Ah + (((size_t)(bA << 9) + sl) << 9) + (k1 & 511));
            else
                av[0] = av[1] = av[2] = av[3] = make_uint4(0, 0, 0, 0);
            ld_kmaj(bx, by, Bh, Ee, k1, kpb, bc + c0);
        }
        mma_core64h(As[buf], Bs[buf], c, g, t, wm, wn);
        if (i + 1 < nIter) {
            st_mmaj(As[nb], tid, av);
            st_kmaj(Bs[nb], kpb, c0, bx, by);
        }
    }

    float cs[16] = {0.f}, cq[16] = {0.f};
    #pragma unroll
    for (int mt = 0; mt < 4; mt++)
        #pragma unroll
        for (int i = 0; i < 2; i++) {
            const int rowo = br + wm + mt * 16 + g + 8 * i;
            const int l = rowo & 511;
            #pragma unroll
            for (int nt = 0; nt < 8; nt++) {
                const int col = bc + wn + nt * 8 + 2 * t;
                float2 bvv = *(const float2*)(kb + (size_t)l * 512 + col);
                float2 v;
                v.x = c[mt][nt][2 * i + 0] + bvv.x;
                v.y = c[mt][nt][2 * i + 1] + bvv.y;
                cs[nt * 2 + 0] += v.x; cq[nt * 2 + 0] += v.x * v.x;
                cs[nt * 2 + 1] += v.y; cq[nt * 2 + 1] += v.y * v.y;
                *(float2*)(C + (size_t)rowo * 512 + col) = v;
            }
        }
    colstats_epilogue(ssum, ssq, cs, cq, g, t, bc + wn);
}

// Fused NN GEMMs (z=0: q2 = l@wq + qb ; z=1: k2 = l@wk + kb). Col stats fused.
__global__ void __launch_bounds__(128) k_gemm_nn(const __half* __restrict__ Ah,
                                                 const __half* __restrict__ Bqh,
                                                 const __half* __restrict__ Bkh,
                                                 const float* __restrict__ biasq,
                                                 const float* __restrict__ biask,
                                                 float* __restrict__ Cq,
                                                 float* __restrict__ Ck,
                                                 float* __restrict__ stats) {
    const __half* Bh = blockIdx.z ? Bkh : Bqh;
    const float* bias = blockIdx.z ? biask : biasq;
    float* C = blockIdx.z ? Ck : Cq;
    float* ssum = stats + (blockIdx.z ? 4 * Ee : 2 * Ee);
    float* ssq = ssum + Ee;
    __shared__ uint32_t As[2][16][PADW];
    __shared__ uint32_t Bs[2][16][PADW];
    float c[4][8][4] = {{{0.f}}};
    const int tid = threadIdx.x;
    const int lane = tid & 31, wid = tid >> 5;
    const int g = lane >> 2, t = lane & 3;
    const int wm = (wid & 1) << 6, wn = (wid >> 1) << 6;
    const int br = blockIdx.y << 7, bc = blockIdx.x << 7;
    const int kpb = tid >> 5, c0 = (tid & 31) << 2;

    uint4 av[4];
    uint2 bx[4], by[4];
    ld_mmaj(av, Ah + (size_t)(br + tid) * 512);
    ld_kmaj(bx, by, Bh, 512, 0, kpb, bc + c0);
    st_mmaj(As[0], tid, av);
    st_kmaj(Bs[0], kpb, c0, bx, by);

    const int nIter = 16;
    for (int i = 0; i < nIter; i++) {
        const int buf = i & 1, nb = buf ^ 1;
        __syncthreads();
        const int k1 = (i + 1) << 5;
        if (i + 1 < nIter) {
            ld_mmaj(av, Ah + (size_t)(br + tid) * 512 + k1);
            ld_kmaj(bx, by, Bh, 512, k1, kpb, bc + c0);
        }
        mma_core64h(As[buf], Bs[buf], c, g, t, wm, wn);
        if (i + 1 < nIter) {
            st_mmaj(As[nb], tid, av);
            st_kmaj(Bs[nb], kpb, c0, bx, by);
        }
    }

    float cs[16] = {0.f}, cq[16] = {0.f};
    #pragma unroll
    for (int mt = 0; mt < 4; mt++)
        #pragma unroll
        for (int i = 0; i < 2; i++) {
            const int rowo = br + wm + mt * 16 + g + 8 * i;
            const int l = rowo & 511;
            #pragma unroll
            for (int nt = 0; nt < 8; nt++) {
                const int col = bc + wn + nt * 8 + 2 * t;
                float2 bvv = *(const float2*)(bias + (size_t)l * 512 + col);
                float2 v;
                v.x = c[mt][nt][2 * i + 0] + bvv.x;
                v.y = c[mt][nt][2 * i + 1] + bvv.y;
                cs[nt * 2 + 0] += v.x; cq[nt * 2 + 0] += v.x * v.x;
                cs[nt * 2 + 1] += v.y; cq[nt * 2 + 1] += v.y * v.y;
                *(float2*)(C + (size_t)rowo * 512 + col) = v;
            }
        }
    colstats_epilogue(ssum, ssq, cs, cq, g, t, bc + wn);
}

// Batched NT: C[k,q] = sum_e k2[k,e]*q2[q,e] + wbT. Both m-major. Row stats.
__global__ void __launch_bounds__(128) k_gemm_nt(const __half* __restrict__ Ain,
                                                 const __half* __restrict__ Bin,
                                                 const float* __restrict__ wbT,
                                                 float* __restrict__ Cout,
                                                 float* __restrict__ rsum,
                                                 float* __restrict__ rsq) {
    const int bz = blockIdx.z;
    const __half* A = Ain + (size_t)bz * Ll * Ee;
    const __half* Bm = Bin + (size_t)bz * Ll * Ee;
    float* C = Cout + (size_t)bz * Ll * Ll;
    __shared__ uint32_t As[2][16][PADW];
    __shared__ uint32_t Bs[2][16][PADW];
    float c[4][8][4] = {{{0.f}}};
    const int tid = threadIdx.x;
    const int lane = tid & 31, wid = tid >> 5;
    const int g = lane >> 2, t = lane & 3;
    const int wm = (wid & 1) << 6, wn = (wid >> 1) << 6;
    const int br = blockIdx.y << 7, bc = blockIdx.x << 7;

    uint4 av[4], bv[4];
    ld_mmaj(av, A + (size_t)(br + tid) * 512);
    ld_mmaj(bv, Bm + (size_t)(bc + tid) * 512);
    st_mmaj(As[0], tid, av);
    st_mmaj(Bs[0], tid, bv);

    const int nIter = 16;
    for (int i = 0; i < nIter; i++) {
        const int buf = i & 1, nb = buf ^ 1;
        __syncthreads();
        const int k1 = (i + 1) << 5;
        if (i + 1 < nIter) {
            ld_mmaj(av, A + (size_t)(br + tid) * 512 + k1);
            ld_mmaj(bv, Bm + (size_t)(bc + tid) * 512 + k1);
        }
        mma_core64h(As[buf], Bs[buf], c, g, t, wm, wn);
        if (i + 1 < nIter) {
            st_mmaj(As[nb], tid, av);
            st_mmaj(Bs[nb], tid, bv);
        }
    }

    float rs[8] = {0.f}, rq[8] = {0.f};
    #pragma unroll
    for (int mt = 0; mt < 4; mt++)
        #pragma unroll
        for (int i = 0; i < 2; i++) {
            const int rowo = br + wm + mt * 16 + g + 8 * i;
            #pragma unroll
            for (int nt = 0; nt < 8; nt++) {
                const int col = bc + wn + nt * 8 + 2 * t;
                float2 bv2 = *(const float2*)(wbT + (size_t)rowo * 512 + col);
                float2 v;
                v.x = c[mt][nt][2 * i + 0] + bv2.x;
                v.y = c[mt][nt][2 * i + 1] + bv2.y;
                rs[mt * 2 + i] += v.x + v.y;
                rq[mt * 2 + i] += v.x * v.x + v.y * v.y;
                *(float2*)(C + (size_t)rowo * 512 + col) = v;
            }
        }
    #pragma unroll
    for (int x = 0; x < 8; x++) {
        float s = rs[x], q = rq[x];
        s += __shfl_xor_sync(0xffffffffu, s, 1); q += __shfl_xor_sync(0xffffffffu, q, 1);
        s += __shfl_xor_sync(0xffffffffu, s, 2); q += __shfl_xor_sync(0xffffffffu, q, 2);
        if (t == 0) {
            const int rowo = br + wm + (x >> 1) * 16 + g + 8 * (x & 1);
            atomicAdd(&rsum[rowo], s);
            atomicAdd(&rsq[rowo], q);
        }
    }
}

// Batched TN: C[q,e] = sum_k wh[k,q]*lh[k,e]. Both k-major. Col stats fused.
__global__ void __launch_bounds__(128) k_gemm_tn(const __half* __restrict__ Ain,
                                                 const __half* __restrict__ Bin,
                                                 float* __restrict__ Cout,
                                                 float* __restrict__ ssum,
                                                 float* __restrict__ ssq) {
    const int bz = blockIdx.z;
    const __half* A = Ain + (size_t)bz * Ll * Ll;
    const __half* Bm = Bin + (size_t)bz * Ll * Ee;
    float* C = Cout + (size_t)bz * Ll * Ee;
    __shared__ uint32_t As[2][16][PADW];
    __shared__ uint32_t Bs[2][16][PADW];
    float c[4][8][4] = {{{0.f}}};
    const int tid = threadIdx.x;
    const int lane = tid & 31, wid = tid >> 5;
    const int g = lane >> 2, t = lane & 3;
    const int wm = (wid & 1) << 6, wn = (wid >> 1) << 6;
    const int br = blockIdx.y << 7, bc = blockIdx.x << 7;
    const int kpb = tid >> 5, c0 = (tid & 31) << 2;

    uint2 ax[4], ay[4], bx[4], by[4];
    ld_kmaj(ax, ay, A, 512, 0, kpb, br + c0);
    ld_kmaj(bx, by, Bm, 512, 0, kpb, bc + c0);
    st_kmaj(As[0], kpb, c0, ax, ay);
    st_kmaj(Bs[0], kpb, c0, bx, by);

    const int nIter = 16;
    for (int i = 0; i < nIter; i++) {
        const int buf = i & 1, nb = buf ^ 1;
        __syncthreads();
        const int k1 = (i + 1) << 5;
        if (i + 1 < nIter) {
            ld_kmaj(ax, ay, A, 512, k1, kpb, br + c0);
            ld_kmaj(bx, by, Bm, 512, k1, kpb, bc + c0);
        }
        mma_core64h(As[buf], Bs[buf], c, g, t, wm, wn);
        if (i + 1 < nIter) {
            st_kmaj(As[nb], kpb, c0, ax, ay);
            st_kmaj(Bs[nb], kpb, c0, bx, by);
        }
    }

    float cs[16] = {0.f}, cq[16] = {0.f};
    #pragma unroll
    for (int mt = 0; mt < 4; mt++)
        #pragma unroll
        for (int i = 0; i < 2; i++) {
            const int rowo = br + wm + mt * 16 + g + 8 * i;
            #pragma unroll
            for (int nt = 0; nt < 8; nt++) {
                const int col = bc + wn + nt * 8 + 2 * t;
                float2 v;
                v.x = c[mt][nt][2 * i + 0];
                v.y = c[mt][nt][2 * i + 1];
                cs[nt * 2 + 0] += v.x; cq[nt * 2 + 0] += v.x * v.x;
                cs[nt * 2 + 1] += v.y; cq[nt * 2 + 1] += v.y * v.y;
                *(float2*)(C + (size_t)rowo * 512 + col) = v;
            }
        }
    colstats_epilogue(ssum, ssq, cs, cq, g, t, bc + wn);
}

extern "C" void kernel_launch(void* const* d_in, const int* in_sizes, int n_in,
                              void* d_out, int out_size) {
    const float* m1 = (const float*)d_in[0];
    const float* f  = (const float*)d_in[1];
    const float* wq = (const float*)d_in[2];
    const float* wk = (const float*)d_in[3];
    const float* qb = (const float*)d_in[4];
    const float* kb = (const float*)d_in[5];
    const float* wb = (const float*)d_in[6];
    const float* g1 = (const float*)d_in[7];  const float* b1 = (const float*)d_in[8];
    const float* g2 = (const float*)d_in[9];  const float* b2 = (const float*)d_in[10];
    const float* g3 = (const float*)d_in[11]; const float* b3 = (const float*)d_in[12];
    const float* g4 = (const float*)d_in[13]; const float* b4 = (const float*)d_in[14];
    const float* g5 = (const float*)d_in[15]; const float* b5 = (const float*)d_in[16];

    float *pl, *pq, *pk, *pw, *po, *ps, *pwbT;
    __half *pm1h, *pfh, *pwqh, *pwkh, *plh, *pqh, *pkh, *pwh;
    cudaGetSymbolAddress((void**)&pl, g_l);
    cudaGetSymbolAddress((void**)&pq, g_q);
    cudaGetSymbolAddress((void**)&pk, g_k);
    cudaGetSymbolAddress((void**)&pw, g_w);
    cudaGetSymbolAddress((void**)&po, g_o);
    cudaGetSymbolAddress((void**)&ps, g_s);
    cudaGetSymbolAddress((void**)&pwbT, g_wbT);
    cudaGetSymbolAddress((void**)&pm1h, g_m1h);
    cudaGetSymbolAddress((void**)&pfh, g_fh);
    cudaGetSymbolAddress((void**)&pwqh, g_wqh);
    cudaGetSymbolAddress((void**)&pwkh, g_wkh);
    cudaGetSymbolAddress((void**)&plh, g_lh);
    cudaGetSymbolAddress((void**)&pqh, g_qh);
    cudaGetSymbolAddress((void**)&pkh, g_kh);
    cudaGetSymbolAddress((void**)&pwh, g_wh);

    const int T = 256, TG = 128;

    // fused pre-pass (stats zero + all fp32->fp16 conversions) + wb transpose
    k_prep<<<(N_PREP + 255) / 256, T>>>((const float4*)m1, (uint2*)pm1h,
                                        (const float4*)f, (uint2*)pfh,
                                        (const float4*)wq, (uint2*)pwqh,
                                        (const float4*)wk, (uint2*)pwkh,
                                        (float4*)ps);
    k_transpose<<<dim3(16, 16), dim3(32, 8)>>>(wb, pwbT);

    // 1) l_pre = unfold(m1) @ f + kb ; BN1+ELU -> half
    k_gemm1<<<dim3(4, 128), TG>>>(pm1h, pfh, kb, pl, ps + 0 * Ee, ps + 1 * Ee);
    k_bn_elu<true><<<2048, T>>>((const float4*)pl, plh,
                                (const float4*)(ps + 0 * Ee), (const float4*)(ps + 1 * Ee),
                                (const float4*)g1, (const float4*)b1);

    // 2) q2 / k2 ; merged BN+ELU -> half
    k_gemm_nn<<<dim3(4, 128, 2), TG>>>(plh, pwqh, pwkh, qb, kb, pq, pk, ps);
    k_bn_elu_qk<<<dim3(2048, 2), T>>>((const float4*)pq, (uint2*)pqh,
                                      (const float4*)pk, (uint2*)pkh, ps,
                                      (const float4*)g2, (const float4*)b2,
                                      (const float4*)g3, (const float4*)b3);

    // 3) wT = k2 @ q2^T + wbT ; BN4 + softmax -> half
    k_gemm_nt<<<dim3(4, 4, 32), TG>>>(pkh, pqh, pwbT, pw, ps + 8 * Ee, ps + 9 * Ee);
    k_bn_softmax<<<16384, T>>>(pw, pwh, ps + 8 * Ee, ps + 9 * Ee, g4, b4);

    // 4) out = wT^T @ l ; BN5 + ELU -> d_out (fp32)
    k_gemm_tn<<<dim3(4, 4, 32), TG>>>(pwh, plh, po, ps + 6 * Ee, ps + 7 * Ee);
    k_bn_elu<false><<<2048, T>>>((const float4*)po, d_out,
                                 (const float4*)(ps + 6 * Ee), (const float4*)(ps + 7 * Ee),
                                 (const float4*)g5, (const float4*)b5);
}

// round 15
// speedup vs baseline: 1.2115x; 1.0542x over previous
#include <cuda_runtime.h>
#include <cuda_fp16.h>
#include <math.h>
#include <stdint.h>

#define Bb 32
#define Ll 512
#define Ee 512
#define RR (Bb*Ll)
#define KE (5*Ee)
#define EPSV 1e-3f
#define PADW 136

// fp32 scratch (pre-BN activations for exact stats)
__device__ float g_l[RR*Ee];
__device__ float g_q[RR*Ee];
__device__ float g_k[RR*Ee];
__device__ float g_w[Bb*Ll*Ll];     // wT[b,k,q] pre-BN fp32
__device__ float g_o[RR*Ee];
__device__ float g_wbT[Ll*Ll];
__device__ float g_s[10*Ee];
// fp16 operands
__device__ __half g_m1h[RR*Ee];
__device__ __half g_fh[KE*Ee];
__device__ __half g_wqh[Ee*Ee];
__device__ __half g_wkh[Ee*Ee];
__device__ __half g_lh[RR*Ee];
__device__ __half g_qh[RR*Ee];
__device__ __half g_kh[RR*Ee];
__device__ __half g_wh[Bb*Ll*Ll];

__device__ __forceinline__ uint32_t pack2(float a, float b) {
    __half2 h = __floats2half2_rn(a, b);
    return *(uint32_t*)&h;
}
__device__ __forceinline__ float elu_fast(float y) {
    return y > 0.f ? y : (__expf(y) - 1.f);
}

// ---------------------------------------------------------------------------
// fp16 mma core: 64x64 warp tile over [16][PADW] kpair-word tiles, BK=32.
// ---------------------------------------------------------------------------
__device__ __forceinline__ void mma_core64h(const uint32_t (*As)[PADW],
                                            const uint32_t (*Bs)[PADW],
                                            float c[4][8][4],
                                            int g, int t, int wm, int wn) {
    #pragma unroll
    for (int ks = 0; ks < 2; ks++) {
        const int kb = ks * 8;
        uint32_t a[4][4], b[8][2];
        #pragma unroll
        for (int mt = 0; mt < 4; mt++) {
            const int m = wm + mt * 16 + g;
            a[mt][0] = As[kb + t][m];
            a[mt][1] = As[kb + t][m + 8];
            a[mt][2] = As[kb + t + 4][m];
            a[mt][3] = As[kb + t + 4][m + 8];
        }
        #pragma unroll
        for (int nt = 0; nt < 8; nt++) {
            const int n = wn + nt * 8 + g;
            b[nt][0] = Bs[kb + t][n];
            b[nt][1] = Bs[kb + t + 4][n];
        }
        #pragma unroll
        for (int mt = 0; mt < 4; mt++)
            #pragma unroll
            for (int nt = 0; nt < 8; nt++)
                asm volatile(
                    "mma.sync.aligned.m16n8k16.row.col.f32.f16.f16.f32 "
                    "{%0,%1,%2,%3},{%4,%5,%6,%7},{%8,%9},{%0,%1,%2,%3};"
                    : "+f"(c[mt][nt][0]), "+f"(c[mt][nt][1]),
                      "+f"(c[mt][nt][2]), "+f"(c[mt][nt][3])
                    : "r"(a[mt][0]), "r"(a[mt][1]), "r"(a[mt][2]), "r"(a[mt][3]),
                      "r"(b[nt][0]), "r"(b[nt][1]));
    }
}

// m-major staging: thread col m = tid, 32 k-contig halves = 4 x uint4.
__device__ __forceinline__ void ld_mmaj(uint4 v[4], const __half* src) {
    const uint4* p = (const uint4*)src;
    v[0] = p[0]; v[1] = p[1]; v[2] = p[2]; v[3] = p[3];
}
__device__ __forceinline__ void st_mmaj(uint32_t (*S)[PADW], int m, const uint4 v[4]) {
    #pragma unroll
    for (int u = 0; u < 4; u++) {
        S[4*u + 0][m] = v[u].x;
        S[4*u + 1][m] = v[u].y;
        S[4*u + 2][m] = v[u].z;
        S[4*u + 3][m] = v[u].w;
    }
}
// k-major staging: thread covers colquad c0 = 4*(tid&31), kp = (tid>>5)+4j.
__device__ __forceinline__ void ld_kmaj(uint2 x[4], uint2 y[4], const __half* B,
                                        int ld, int k0, int kpb, int gcol) {
    #pragma unroll
    for (int j = 0; j < 4; j++) {
        const __half* r = B + (size_t)(k0 + 2 * (kpb + 4 * j)) * ld + gcol;
        x[j] = *(const uint2*)r;
        y[j] = *(const uint2*)(r + ld);
    }
}
__device__ __forceinline__ void st_kmaj(uint32_t (*S)[PADW], int kpb, int c0,
                                        const uint2 x[4], const uint2 y[4]) {
    #pragma unroll
    for (int j = 0; j < 4; j++) {
        const int kp = kpb + 4 * j;
        uint4 w;
        w.x = __byte_perm(x[j].x, y[j].x, 0x5410);
        w.y = __byte_perm(x[j].x, y[j].x, 0x7632);
        w.z = __byte_perm(x[j].y, y[j].y, 0x5410);
        w.w = __byte_perm(x[j].y, y[j].y, 0x7632);
        *(uint4*)&S[kp][c0] = w;
    }
}

__device__ __forceinline__ void colstats_epilogue(float* __restrict__ sum,
                                                  float* __restrict__ sumsq,
                                                  const float cs[16], const float cq[16],
                                                  int g, int t, int bcwn) {
    #pragma unroll
    for (int x = 0; x < 16; x++) {
        float s = cs[x], q = cq[x];
        s += __shfl_xor_sync(0xffffffffu, s, 4);  q += __shfl_xor_sync(0xffffffffu, q, 4);
        s += __shfl_xor_sync(0xffffffffu, s, 8);  q += __shfl_xor_sync(0xffffffffu, q, 8);
        s += __shfl_xor_sync(0xffffffffu, s, 16); q += __shfl_xor_sync(0xffffffffu, q, 16);
        if (g == 0) {
            const int col = bcwn + (x >> 1) * 8 + 2 * t + (x & 1);
            atomicAdd(&sum[col], s);
            atomicAdd(&sumsq[col], q);
        }
    }
}
__device__ __forceinline__ float blockReduceSum(float v, float* sh) {
    const int t = threadIdx.x;
    #pragma unroll
    for (int o = 16; o > 0; o >>= 1) v += __shfl_xor_sync(0xffffffffu, v, o);
    if ((t & 31) == 0) sh[t >> 5] = v;
    __syncthreads();
    if (t < 32) {
        v = (t < (int)(blockDim.x >> 5)) ? sh[t] : 0.f;
        #pragma unroll
        for (int o = 16; o > 0; o >>= 1) v += __shfl_xor_sync(0xffffffffu, v, o);
        if (t == 0) sh[0] = v;
    }
    __syncthreads();
    float r = sh[0];
    __syncthreads();
    return r;
}
__device__ __forceinline__ float blockReduceMax(float v, float* sh) {
    const int t = threadIdx.x;
    #pragma unroll
    for (int o = 16; o > 0; o >>= 1) v = fmaxf(v, __shfl_xor_sync(0xffffffffu, v, o));
    if ((t & 31) == 0) sh[t >> 5] = v;
    __syncthreads();
    if (t < 32) {
        v = (t < (int)(blockDim.x >> 5)) ? sh[t] : -INFINITY;
        #pragma unroll
        for (int o = 16; o > 0; o >>= 1) v = fmaxf(v, __shfl_xor_sync(0xffffffffu, v, o));
        if (t == 0) sh[0] = v;
    }
    __syncthreads();
    float r = sh[0];
    __syncthreads();
    return r;
}

// Fused pre-pass: zero stats + fp32->fp16 for m1 / f / wq / wk (region split).
#define N_M1 (RR*Ee/4)
#define N_F  (KE*Ee/4)
#define N_W  (Ee*Ee/4)
#define N_PREP (N_M1 + N_F + 2*N_W)
__global__ void __launch_bounds__(256) k_prep(const float4* __restrict__ m1,
                                              uint2* __restrict__ m1h,
                                              const float4* __restrict__ f,
                                              uint2* __restrict__ fh,
                                              const float4* __restrict__ wq,
                                              uint2* __restrict__ wqh,
                                              const float4* __restrict__ wk,
                                              uint2* __restrict__ wkh,
                                              float4* __restrict__ ps4) {
    const int i = blockIdx.x * 256 + threadIdx.x;
    if (i < 10 * Ee / 4) ps4[i] = make_float4(0.f, 0.f, 0.f, 0.f);
    const float4* src;
    uint2* dst;
    int j = i;
    if (j < N_M1) { src = m1; dst = m1h; }
    else {
        j -= N_M1;
        if (j < N_F) { src = f; dst = fh; }
        else {
            j -= N_F;
            if (j < N_W) { src = wq; dst = wqh; }
            else { j -= N_W; if (j >= N_W) return; src = wk; dst = wkh; }
        }
    }
    float4 v = src[j];
    uint2 o;
    o.x = pack2(v.x, v.y);
    o.y = pack2(v.z, v.w);
    dst[j] = o;
}

__global__ void k_transpose(const float* __restrict__ src, float* __restrict__ dst) {
    __shared__ float tile[32][33];
    const int bx = blockIdx.x << 5, by = blockIdx.y << 5;
    #pragma unroll
    for (int j = 0; j < 4; j++)
        tile[threadIdx.y + j * 8][threadIdx.x] =
            src[(size_t)(by + threadIdx.y + j * 8) * 512 + bx + threadIdx.x];
    __syncthreads();
    #pragma unroll
    for (int j = 0; j < 4; j++)
        dst[(size_t)(bx + threadIdx.y + j * 8) * 512 + by + threadIdx.x] =
            tile[threadIdx.x][threadIdx.y + j * 8];
}

// BN + ELU; HOUT: write half, else fp32. Per-column constants hoisted
// (grid stride 2048*256 is a multiple of 128 -> c4 invariant per thread).
template<bool HOUT>
__global__ void __launch_bounds__(256) k_bn_elu(const float4* __restrict__ X,
                                                void* __restrict__ Y,
                                                const float4* __restrict__ sum4,
                                                const float4* __restrict__ sumsq4,
                                                const float4* __restrict__ g4,
                                                const float4* __restrict__ bt4) {
    const float invN = 1.f / (float)RR;
    const int total4 = RR * Ee / 4;
    const int i0 = blockIdx.x * blockDim.x + threadIdx.x;
    const int c4 = i0 & 127;
    float4 sm = sum4[c4], sq = sumsq4[c4], gg = g4[c4], bb = bt4[c4];
    float4 scv, shv;
    {
        float m, va;
        m = sm.x * invN; va = sq.x * invN - m * m;
        scv.x = gg.x * rsqrtf(va + EPSV); shv.x = bb.x - m * scv.x;
        m = sm.y * invN; va = sq.y * invN - m * m;
        scv.y = gg.y * rsqrtf(va + EPSV); shv.y = bb.y - m * scv.y;
        m = sm.z * invN; va = sq.z * invN - m * m;
        scv.z = gg.z * rsqrtf(va + EPSV); shv.z = bb.z - m * scv.z;
        m = sm.w * invN; va = sq.w * invN - m * m;
        scv.w = gg.w * rsqrtf(va + EPSV); shv.w = bb.w - m * scv.w;
    }
    for (int i = i0; i < total4; i += gridDim.x * blockDim.x) {
        float4 v = X[i];
        float4 o;
        o.x = elu_fast(v.x * scv.x + shv.x);
        o.y = elu_fast(v.y * scv.y + shv.y);
        o.z = elu_fast(v.z * scv.z + shv.z);
        o.w = elu_fast(v.w * scv.w + shv.w);
        if (HOUT) {
            uint2 u;
            u.x = pack2(o.x, o.y);
            u.y = pack2(o.z, o.w);
            ((uint2*)Y)[i] = u;
        } else {
            ((float4*)Y)[i] = o;
        }
    }
}

// Merged BN+ELU for q (y=0) and k (y=1); half output; hoisted constants.
__global__ void __launch_bounds__(256) k_bn_elu_qk(const float4* __restrict__ Xq,
                                                   uint2* __restrict__ Yq,
                                                   const float4* __restrict__ Xk,
                                                   uint2* __restrict__ Yk,
                                                   const float* __restrict__ stats,
                                                   const float4* __restrict__ gq,
                                                   const float4* __restrict__ bq,
                                                   const float4* __restrict__ gk,
                                                   const float4* __restrict__ bk) {
    const int z = blockIdx.y;
    const float4* X = z ? Xk : Xq;
    uint2* Y = z ? Yk : Yq;
    const float4* sum4 = (const float4*)(stats + (z ? 4 * Ee : 2 * Ee));
    const float4* sumsq4 = (const float4*)(stats + (z ? 5 * Ee : 3 * Ee));
    const float4* g4 = z ? gk : gq;
    const float4* bt4 = z ? bk : bq;
    const float invN = 1.f / (float)RR;
    const int total4 = RR * Ee / 4;
    const int i0 = blockIdx.x * blockDim.x + threadIdx.x;
    const int c4 = i0 & 127;
    float4 sm = sum4[c4], sq = sumsq4[c4], gg = g4[c4], bb = bt4[c4];
    float4 scv, shv;
    {
        float m, va;
        m = sm.x * invN; va = sq.x * invN - m * m;
        scv.x = gg.x * rsqrtf(va + EPSV); shv.x = bb.x - m * scv.x;
        m = sm.y * invN; va = sq.y * invN - m * m;
        scv.y = gg.y * rsqrtf(va + EPSV); shv.y = bb.y - m * scv.y;
        m = sm.z * invN; va = sq.z * invN - m * m;
        scv.z = gg.z * rsqrtf(va + EPSV); shv.z = bb.z - m * scv.z;
        m = sm.w * invN; va = sq.w * invN - m * m;
        scv.w = gg.w * rsqrtf(va + EPSV); shv.w = bb.w - m * scv.w;
    }
    for (int i = i0; i < total4; i += gridDim.x * blockDim.x) {
        float4 v = X[i];
        float4 o;
        o.x = elu_fast(v.x * scv.x + shv.x);
        o.y = elu_fast(v.y * scv.y + shv.y);
        o.z = elu_fast(v.z * scv.z + shv.z);
        o.w = elu_fast(v.w * scv.w + shv.w);
        uint2 u;
        u.x = pack2(o.x, o.y);
        u.y = pack2(o.z, o.w);
        Y[i] = u;
    }
}

// BN4 + softmax over q; reads fp32 wT rows, writes half. Fast exp.
__global__ void k_bn_softmax(const float* __restrict__ Wt, __half* __restrict__ Wh,
                             const float* __restrict__ sum, const float* __restrict__ sumsq,
                             const float* __restrict__ g4, const float* __restrict__ b4) {
    const int bk = blockIdx.x;
    const int k = bk & 511;
    const float* row = Wt + ((size_t)bk << 9);
    const float invN = 1.f / (float)RR;
    const float mean = sum[k] * invN;
    const float var = sumsq[k] * invN - mean * mean;
    const float sc = g4[k] * rsqrtf(var + EPSV);
    const float shf = b4[k] - mean * sc;
    const int t = threadIdx.x;
    float2 xv = *(const float2*)(row + 2 * t);
    float x0 = xv.x * sc + shf;
    float x1 = xv.y * sc + shf;
    __shared__ float sh[32];
    float mx = blockReduceMax(fmaxf(x0, x1), sh);
    float e0 = __expf(x0 - mx), e1 = __expf(x1 - mx);
    float tot = blockReduceSum(e0 + e1, sh);
    float inv = 1.f / tot;
    *(uint32_t*)(Wh + ((size_t)bk << 9) + 2 * t) = pack2(e0 * inv, e1 * inv);
}

// ---------------------------------------------------------------------------
// fp16 GEMMs (identical to passing R10/R13 code)
// ---------------------------------------------------------------------------

// GEMM1: C = unfold(m1h) @ fh + kb. A gathered m-major, B k-major. Col stats.
__global__ void __launch_bounds__(128) k_gemm1(const __half* __restrict__ Ah,
                                               const __half* __restrict__ Bh,
                                               const float* __restrict__ kb,
                                               float* __restrict__ C,
                                               float* __restrict__ ssum,
                                               float* __restrict__ ssq) {
    __shared__ uint32_t As[2][16][PADW];
    __shared__ uint32_t Bs[2][16][PADW];
    float c[4][8][4] = {{{0.f}}};
    const int tid = threadIdx.x;
    const int lane = tid & 31, wid = tid >> 5;
    const int g = lane >> 2, t = lane & 3;
    const int wm = (wid & 1) << 6, wn = (wid >> 1) << 6;
    const int br = blockIdx.y << 7, bc = blockIdx.x << 7;
    const int kpb = tid >> 5, c0 = (tid & 31) << 2;

    const int row = br + tid;
    const int bA = row >> 9, lA = row & 511;

    uint4 av[4];
    uint2 bx[4], by[4];
    {
        const int sl = lA - 2;
        if ((unsigned)sl < 512u)
            ld_mmaj(av, Ah + (((size_t)(bA << 9) + sl) << 9));
        else
            av[0] = av[1] = av[2] = av[3] = make_uint4(0, 0, 0, 0);
        ld_kmaj(bx, by, Bh, Ee, 0, kpb, bc + c0);
    }
    st_mmaj(As[0], tid, av);
    st_kmaj(Bs[0], kpb, c0, bx, by);

    const int nIter = KE / 32;
    for (int i = 0; i < nIter; i++) {
        const int buf = i & 1, nb = buf ^ 1;
        __syncthreads();
        const int k1 = (i + 1) << 5;
        if (i + 1 < nIter) {
            const int sl = lA + (k1 >> 9) - 2;
            if ((unsigned)sl < 512u)
                ld_mmaj(av, Ah + (((size_t)(bA << 9) + sl) << 9) + (k1 & 511));
            else
                av[0] = av[1] = av[2] = av[3] = make_uint4(0, 0, 0, 0);
            ld_kmaj(bx, by, Bh, Ee, k1, kpb, bc + c0);
        }
        mma_core64h(As[buf], Bs[buf], c, g, t, wm, wn);
        if (i + 1 < nIter) {
            st_mmaj(As[nb], tid, av);
            st_kmaj(Bs[nb], kpb, c0, bx, by);
        }
    }

    float cs[16] = {0.f}, cq[16] = {0.f};
    #pragma unroll
    for (int mt = 0; mt < 4; mt++)
        #pragma unroll
        for (int i = 0; i < 2; i++) {
            const int rowo = br + wm + mt * 16 + g + 8 * i;
            const int l = rowo & 511;
            #pragma unroll
            for (int nt = 0; nt < 8; nt++) {
                const int col = bc + wn + nt * 8 + 2 * t;
                float2 bvv = *(const float2*)(kb + (size_t)l * 512 + col);
                float2 v;
                v.x = c[mt][nt][2 * i + 0] + bvv.x;
                v.y = c[mt][nt][2 * i + 1] + bvv.y;
                cs[nt * 2 + 0] += v.x; cq[nt * 2 + 0] += v.x * v.x;
                cs[nt * 2 + 1] += v.y; cq[nt * 2 + 1] += v.y * v.y;
                *(float2*)(C + (size_t)rowo * 512 + col) = v;
            }
        }
    colstats_epilogue(ssum, ssq, cs, cq, g, t, bc + wn);
}

// Fused NN GEMMs (z=0: q2 = l@wq + qb ; z=1: k2 = l@wk + kb). Col stats fused.
__global__ void __launch_bounds__(128) k_gemm_nn(const __half* __restrict__ Ah,
                                                 const __half* __restrict__ Bqh,
                                                 const __half* __restrict__ Bkh,
                                                 const float* __restrict__ biasq,
                                                 const float* __restrict__ biask,
                                                 float* __restrict__ Cq,
                                                 float* __restrict__ Ck,
                                                 float* __restrict__ stats) {
    const __half* Bh = blockIdx.z ? Bkh : Bqh;
    const float* bias = blockIdx.z ? biask : biasq;
    float* C = blockIdx.z ? Ck : Cq;
    float* ssum = stats + (blockIdx.z ? 4 * Ee : 2 * Ee);
    float* ssq = ssum + Ee;
    __shared__ uint32_t As[2][16][PADW];
    __shared__ uint32_t Bs[2][16][PADW];
    float c[4][8][4] = {{{0.f}}};
    const int tid = threadIdx.x;
    const int lane = tid & 31, wid = tid >> 5;
    const int g = lane >> 2, t = lane & 3;
    const int wm = (wid & 1) << 6, wn = (wid >> 1) << 6;
    const int br = blockIdx.y << 7, bc = blockIdx.x << 7;
    const int kpb = tid >> 5, c0 = (tid & 31) << 2;

    uint4 av[4];
    uint2 bx[4], by[4];
    ld_mmaj(av, Ah + (size_t)(br + tid) * 512);
    ld_kmaj(bx, by, Bh, 512, 0, kpb, bc + c0);
    st_mmaj(As[0], tid, av);
    st_kmaj(Bs[0], kpb, c0, bx, by);

    const int nIter = 16;
    for (int i = 0; i < nIter; i++) {
        const int buf = i & 1, nb = buf ^ 1;
        __syncthreads();
        const int k1 = (i + 1) << 5;
        if (i + 1 < nIter) {
            ld_mmaj(av, Ah + (size_t)(br + tid) * 512 + k1);
            ld_kmaj(bx, by, Bh, 512, k1, kpb, bc + c0);
        }
        mma_core64h(As[buf], Bs[buf], c, g, t, wm, wn);
        if (i + 1 < nIter) {
            st_mmaj(As[nb], tid, av);
            st_kmaj(Bs[nb], kpb, c0, bx, by);
        }
    }

    float cs[16] = {0.f}, cq[16] = {0.f};
    #pragma unroll
    for (int mt = 0; mt < 4; mt++)
        #pragma unroll
        for (int i = 0; i < 2; i++) {
            const int rowo = br + wm + mt * 16 + g + 8 * i;
            const int l = rowo & 511;
            #pragma unroll
            for (int nt = 0; nt < 8; nt++) {
                const int col = bc + wn + nt * 8 + 2 * t;
                float2 bvv = *(const float2*)(bias + (size_t)l * 512 + col);
                float2 v;
                v.x = c[mt][nt][2 * i + 0] + bvv.x;
                v.y = c[mt][nt][2 * i + 1] + bvv.y;
                cs[nt * 2 + 0] += v.x; cq[nt * 2 + 0] += v.x * v.x;
                cs[nt * 2 + 1] += v.y; cq[nt * 2 + 1] += v.y * v.y;
                *(float2*)(C + (size_t)rowo * 512 + col) = v;
            }
        }
    colstats_epilogue(ssum, ssq, cs, cq, g, t, bc + wn);
}

// Batched NT: C[k,q] = sum_e k2[k,e]*q2[q,e] + wbT. Both m-major. Row stats.
__global__ void __launch_bounds__(128) k_gemm_nt(const __half* __restrict__ Ain,
                                                 const __half* __restrict__ Bin,
                                                 const float* __restrict__ wbT,
                                                 float* __restrict__ Cout,
                                                 float* __restrict__ rsum,
                                                 float* __restrict__ rsq) {
    const int bz = blockIdx.z;
    const __half* A = Ain + (size_t)bz * Ll * Ee;
    const __half* Bm = Bin + (size_t)bz * Ll * Ee;
    float* C = Cout + (size_t)bz * Ll * Ll;
    __shared__ uint32_t As[2][16][PADW];
    __shared__ uint32_t Bs[2][16][PADW];
    float c[4][8][4] = {{{0.f}}};
    const int tid = threadIdx.x;
    const int lane = tid & 31, wid = tid >> 5;
    const int g = lane >> 2, t = lane & 3;
    const int wm = (wid & 1) << 6, wn = (wid >> 1) << 6;
    const int br = blockIdx.y << 7, bc = blockIdx.x << 7;

    uint4 av[4], bv[4];
    ld_mmaj(av, A + (size_t)(br + tid) * 512);
    ld_mmaj(bv, Bm + (size_t)(bc + tid) * 512);
    st_mmaj(As[0], tid, av);
    st_mmaj(Bs[0], tid, bv);

    const int nIter = 16;
    for (int i = 0; i < nIter; i++) {
        const int buf = i & 1, nb = buf ^ 1;
        __syncthreads();
        const int k1 = (i + 1) << 5;
        if (i + 1 < nIter) {
            ld_mmaj(av, A + (size_t)(br + tid) * 512 + k1);
            ld_mmaj(bv, Bm + (size_t)(bc + tid) * 512 + k1);
        }
        mma_core64h(As[buf], Bs[buf], c, g, t, wm, wn);
        if (i + 1 < nIter) {
            st_mmaj(As[nb], tid, av);
            st_mmaj(Bs[nb], tid, bv);
        }
    }

    float rs[8] = {0.f}, rq[8] = {0.f};
    #pragma unroll
    for (int mt = 0; mt < 4; mt++)
        #pragma unroll
        for (int i = 0; i < 2; i++) {
            const int rowo = br + wm + mt * 16 + g + 8 * i;
            #pragma unroll
            for (int nt = 0; nt < 8; nt++) {
                const int col = bc + wn + nt * 8 + 2 * t;
                float2 bv2 = *(const float2*)(wbT + (size_t)rowo * 512 + col);
                float2 v;
                v.x = c[mt][nt][2 * i + 0] + bv2.x;
                v.y = c[mt][nt][2 * i + 1] + bv2.y;
                rs[mt * 2 + i] += v.x + v.y;
                rq[mt * 2 + i] += v.x * v.x + v.y * v.y;
                *(float2*)(C + (size_t)rowo * 512 + col) = v;
            }
        }
    #pragma unroll
    for (int x = 0; x < 8; x++) {
        float s = rs[x], q = rq[x];
        s += __shfl_xor_sync(0xffffffffu, s, 1); q += __shfl_xor_sync(0xffffffffu, q, 1);
        s += __shfl_xor_sync(0xffffffffu, s, 2); q += __shfl_xor_sync(0xffffffffu, q, 2);
        if (t == 0) {
            const int rowo = br + wm + (x >> 1) * 16 + g + 8 * (x & 1);
            atomicAdd(&rsum[rowo], s);
            atomicAdd(&rsq[rowo], q);
        }
    }
}

// Batched TN: C[q,e] = sum_k wh[k,q]*lh[k,e]. Both k-major. Col stats fused.
__global__ void __launch_bounds__(128) k_gemm_tn(const __half* __restrict__ Ain,
                                                 const __half* __restrict__ Bin,
                                                 float* __restrict__ Cout,
                                                 float* __restrict__ ssum,
                                                 float* __restrict__ ssq) {
    const int bz = blockIdx.z;
    const __half* A = Ain + (size_t)bz * Ll * Ll;
    const __half* Bm = Bin + (size_t)bz * Ll * Ee;
    float* C = Cout + (size_t)bz * Ll * Ee;
    __shared__ uint32_t As[2][16][PADW];
    __shared__ uint32_t Bs[2][16][PADW];
    float c[4][8][4] = {{{0.f}}};
    const int tid = threadIdx.x;
    const int lane = tid & 31, wid = tid >> 5;
    const int g = lane >> 2, t = lane & 3;
    const int wm = (wid & 1) << 6, wn = (wid >> 1) << 6;
    const int br = blockIdx.y << 7, bc = blockIdx.x << 7;
    const int kpb = tid >> 5, c0 = (tid & 31) << 2;

    uint2 ax[4], ay[4], bx[4], by[4];
    ld_kmaj(ax, ay, A, 512, 0, kpb, br + c0);
    ld_kmaj(bx, by, Bm, 512, 0, kpb, bc + c0);
    st_kmaj(As[0], kpb, c0, ax, ay);
    st_kmaj(Bs[0], kpb, c0, bx, by);

    const int nIter = 16;
    for (int i = 0; i < nIter; i++) {
        const int buf = i & 1, nb = buf ^ 1;
        __syncthreads();
        const int k1 = (i + 1) << 5;
        if (i + 1 < nIter) {
            ld_kmaj(ax, ay, A, 512, k1, kpb, br + c0);
            ld_kmaj(bx, by, Bm, 512, k1, kpb, bc + c0);
        }
        mma_core64h(As[buf], Bs[buf], c, g, t, wm, wn);
        if (i + 1 < nIter) {
            st_kmaj(As[nb], kpb, c0, ax, ay);
            st_kmaj(Bs[nb], kpb, c0, bx, by);
        }
    }

    float cs[16] = {0.f}, cq[16] = {0.f};
    #pragma unroll
    for (int mt = 0; mt < 4; mt++)
        #pragma unroll
        for (int i = 0; i < 2; i++) {
            const int rowo = br + wm + mt * 16 + g + 8 * i;
            #pragma unroll
            for (int nt = 0; nt < 8; nt++) {
                const int col = bc + wn + nt * 8 + 2 * t;
                float2 v;
                v.x = c[mt][nt][2 * i + 0];
                v.y = c[mt][nt][2 * i + 1];
                cs[nt * 2 + 0] += v.x; cq[nt * 2 + 0] += v.x * v.x;
                cs[nt * 2 + 1] += v.y; cq[nt * 2 + 1] += v.y * v.y;
                *(float2*)(C + (size_t)rowo * 512 + col) = v;
            }
        }
    colstats_epilogue(ssum, ssq, cs, cq, g, t, bc + wn);
}

extern "C" void kernel_launch(void* const* d_in, const int* in_sizes, int n_in,
                              void* d_out, int out_size) {
    const float* m1 = (const float*)d_in[0];
    const float* f  = (const float*)d_in[1];
    const float* wq = (const float*)d_in[2];
    const float* wk = (const float*)d_in[3];
    const float* qb = (const float*)d_in[4];
    const float* kb = (const float*)d_in[5];
    const float* wb = (const float*)d_in[6];
    const float* g1 = (const float*)d_in[7];  const float* b1 = (const float*)d_in[8];
    const float* g2 = (const float*)d_in[9];  const float* b2 = (const float*)d_in[10];
    const float* g3 = (const float*)d_in[11]; const float* b3 = (const float*)d_in[12];
    const float* g4 = (const float*)d_in[13]; const float* b4 = (const float*)d_in[14];
    const float* g5 = (const float*)d_in[15]; const float* b5 = (const float*)d_in[16];

    float *pl, *pq, *pk, *pw, *po, *ps, *pwbT;
    __half *pm1h, *pfh, *pwqh, *pwkh, *plh, *pqh, *pkh, *pwh;
    cudaGetSymbolAddress((void**)&pl, g_l);
    cudaGetSymbolAddress((void**)&pq, g_q);
    cudaGetSymbolAddress((void**)&pk, g_k);
    cudaGetSymbolAddress((void**)&pw, g_w);
    cudaGetSymbolAddress((void**)&po, g_o);
    cudaGetSymbolAddress((void**)&ps, g_s);
    cudaGetSymbolAddress((void**)&pwbT, g_wbT);
    cudaGetSymbolAddress((void**)&pm1h, g_m1h);
    cudaGetSymbolAddress((void**)&pfh, g_fh);
    cudaGetSymbolAddress((void**)&pwqh, g_wqh);
    cudaGetSymbolAddress((void**)&pwkh, g_wkh);
    cudaGetSymbolAddress((void**)&plh, g_lh);
    cudaGetSymbolAddress((void**)&pqh, g_qh);
    cudaGetSymbolAddress((void**)&pkh, g_kh);
    cudaGetSymbolAddress((void**)&pwh, g_wh);

    const int T = 256, TG = 128;

    k_prep<<<(N_PREP + 255) / 256, T>>>((const float4*)m1, (uint2*)pm1h,
                                        (const float4*)f, (uint2*)pfh,
                                        (const float4*)wq, (uint2*)pwqh,
                                        (const float4*)wk, (uint2*)pwkh,
                                        (float4*)ps);
    k_transpose<<<dim3(16, 16), dim3(32, 8)>>>(wb, pwbT);

    // 1) l_pre = unfold(m1) @ f + kb ; BN1+ELU -> half
    k_gemm1<<<dim3(4, 128), TG>>>(pm1h, pfh, kb, pl, ps + 0 * Ee, ps + 1 * Ee);
    k_bn_elu<true><<<2048, T>>>((const float4*)pl, plh,
                                (const float4*)(ps + 0 * Ee), (const float4*)(ps + 1 * Ee),
                                (const float4*)g1, (const float4*)b1);

    // 2) q2 / k2 ; merged BN+ELU -> half
    k_gemm_nn<<<dim3(4, 128, 2), TG>>>(plh, pwqh, pwkh, qb, kb, pq, pk, ps);
    k_bn_elu_qk<<<dim3(2048, 2), T>>>((const float4*)pq, (uint2*)pqh,
                                      (const float4*)pk, (uint2*)pkh, ps,
                                      (const float4*)g2, (const float4*)b2,
                                      (const float4*)g3, (const float4*)b3);

    // 3) wT = k2 @ q2^T + wbT ; BN4 + softmax -> half
    k_gemm_nt<<<dim3(4, 4, 32), TG>>>(pkh, pqh, pwbT, pw, ps + 8 * Ee, ps + 9 * Ee);
    k_bn_softmax<<<16384, T>>>(pw, pwh, ps + 8 * Ee, ps + 9 * Ee, g4, b4);

    // 4) out = wT^T @ l ; BN5 + ELU -> d_out (fp32)
    k_gemm_tn<<<dim3(4, 4, 32), TG>>>(pwh, plh, po, ps + 6 * Ee, ps + 7 * Ee);
    k_bn_elu<false><<<2048, T>>>((const float4*)po, d_out,
                                 (const float4*)(ps + 6 * Ee), (const float4*)(ps + 7 * Ee),
                                 (const float4*)g5, (const float4*)b5);
}

// round 16
// speedup vs baseline: 1.2441x; 1.0269x over previous
#include <cuda_runtime.h>
#include <cuda_fp16.h>
#include <math.h>
#include <stdint.h>

#define Bb 32
#define Ll 512
#define Ee 512
#define RR (Bb*Ll)
#define KE (5*Ee)
#define EPSV 1e-3f
#define PADW 136

// fp32 scratch (pre-BN activations for exact stats)
__device__ float g_l[RR*Ee];
__device__ float g_q[RR*Ee];
__device__ float g_k[RR*Ee];
__device__ float g_w[Bb*Ll*Ll];     // wT[b,k,q] pre-BN fp32
__device__ float g_o[RR*Ee];
__device__ float g_wbT[Ll*Ll];
__device__ float g_s[10*Ee];
// fp16 operands
__device__ __half g_m1h[RR*Ee];
__device__ __half g_fh[KE*Ee];
__device__ __half g_wqh[Ee*Ee];
__device__ __half g_wkh[Ee*Ee];
__device__ __half g_lh[RR*Ee];
__device__ __half g_qh[RR*Ee];
__device__ __half g_kh[RR*Ee];
__device__ __half g_wh[Bb*Ll*Ll];

__device__ __forceinline__ uint32_t pack2(float a, float b) {
    __half2 h = __floats2half2_rn(a, b);
    return *(uint32_t*)&h;
}
__device__ __forceinline__ float elu_fast(float y) {
    return y > 0.f ? y : (__expf(y) - 1.f);
}

// ---------------------------------------------------------------------------
// fp16 mma core: 64x64 warp tile over [16][PADW] kpair-word tiles, BK=32.
// ---------------------------------------------------------------------------
__device__ __forceinline__ void mma_core64h(const uint32_t (*As)[PADW],
                                            const uint32_t (*Bs)[PADW],
                                            float c[4][8][4],
                                            int g, int t, int wm, int wn) {
    #pragma unroll
    for (int ks = 0; ks < 2; ks++) {
        const int kb = ks * 8;
        uint32_t a[4][4], b[8][2];
        #pragma unroll
        for (int mt = 0; mt < 4; mt++) {
            const int m = wm + mt * 16 + g;
            a[mt][0] = As[kb + t][m];
            a[mt][1] = As[kb + t][m + 8];
            a[mt][2] = As[kb + t + 4][m];
            a[mt][3] = As[kb + t + 4][m + 8];
        }
        #pragma unroll
        for (int nt = 0; nt < 8; nt++) {
            const int n = wn + nt * 8 + g;
            b[nt][0] = Bs[kb + t][n];
            b[nt][1] = Bs[kb + t + 4][n];
        }
        #pragma unroll
        for (int mt = 0; mt < 4; mt++)
            #pragma unroll
            for (int nt = 0; nt < 8; nt++)
                asm volatile(
                    "mma.sync.aligned.m16n8k16.row.col.f32.f16.f16.f32 "
                    "{%0,%1,%2,%3},{%4,%5,%6,%7},{%8,%9},{%0,%1,%2,%3};"
                    : "+f"(c[mt][nt][0]), "+f"(c[mt][nt][1]),
                      "+f"(c[mt][nt][2]), "+f"(c[mt][nt][3])
                    : "r"(a[mt][0]), "r"(a[mt][1]), "r"(a[mt][2]), "r"(a[mt][3]),
                      "r"(b[nt][0]), "r"(b[nt][1]));
    }
}

// m-major staging: thread col m = tid, 32 k-contig halves = 4 x uint4.
__device__ __forceinline__ void ld_mmaj(uint4 v[4], const __half* src) {
    const uint4* p = (const uint4*)src;
    v[0] = p[0]; v[1] = p[1]; v[2] = p[2]; v[3] = p[3];
}
__device__ __forceinline__ void st_mmaj(uint32_t (*S)[PADW], int m, const uint4 v[4]) {
    #pragma unroll
    for (int u = 0; u < 4; u++) {
        S[4*u + 0][m] = v[u].x;
        S[4*u + 1][m] = v[u].y;
        S[4*u + 2][m] = v[u].z;
        S[4*u + 3][m] = v[u].w;
    }
}
// k-major staging: thread covers colquad c0 = 4*(tid&31), kp = (tid>>5)+4j.
__device__ __forceinline__ void ld_kmaj(uint2 x[4], uint2 y[4], const __half* B,
                                        int ld, int k0, int kpb, int gcol) {
    #pragma unroll
    for (int j = 0; j < 4; j++) {
        const __half* r = B + (size_t)(k0 + 2 * (kpb + 4 * j)) * ld + gcol;
        x[j] = *(const uint2*)r;
        y[j] = *(const uint2*)(r + ld);
    }
}
__device__ __forceinline__ void st_kmaj(uint32_t (*S)[PADW], int kpb, int c0,
                                        const uint2 x[4], const uint2 y[4]) {
    #pragma unroll
    for (int j = 0; j < 4; j++) {
        const int kp = kpb + 4 * j;
        uint4 w;
        w.x = __byte_perm(x[j].x, y[j].x, 0x5410);
        w.y = __byte_perm(x[j].x, y[j].x, 0x7632);
        w.z = __byte_perm(x[j].y, y[j].y, 0x5410);
        w.w = __byte_perm(x[j].y, y[j].y, 0x7632);
        *(uint4*)&S[kp][c0] = w;
    }
}

__device__ __forceinline__ void colstats_epilogue(float* __restrict__ sum,
                                                  float* __restrict__ sumsq,
                                                  const float cs[16], const float cq[16],
                                                  int g, int t, int bcwn) {
    #pragma unroll
    for (int x = 0; x < 16; x++) {
        float s = cs[x], q = cq[x];
        s += __shfl_xor_sync(0xffffffffu, s, 4);  q += __shfl_xor_sync(0xffffffffu, q, 4);
        s += __shfl_xor_sync(0xffffffffu, s, 8);  q += __shfl_xor_sync(0xffffffffu, q, 8);
        s += __shfl_xor_sync(0xffffffffu, s, 16); q += __shfl_xor_sync(0xffffffffu, q, 16);
        if (g == 0) {
            const int col = bcwn + (x >> 1) * 8 + 2 * t + (x & 1);
            atomicAdd(&sum[col], s);
            atomicAdd(&sumsq[col], q);
        }
    }
}

// Fused pre-pass: zero stats + fp32->fp16 for m1 / f / wq / wk (region split).
#define N_M1 (RR*Ee/4)
#define N_F  (KE*Ee/4)
#define N_W  (Ee*Ee/4)
#define N_PREP (N_M1 + N_F + 2*N_W)
__global__ void __launch_bounds__(256) k_prep(const float4* __restrict__ m1,
                                              uint2* __restrict__ m1h,
                                              const float4* __restrict__ f,
                                              uint2* __restrict__ fh,
                                              const float4* __restrict__ wq,
                                              uint2* __restrict__ wqh,
                                              const float4* __restrict__ wk,
                                              uint2* __restrict__ wkh,
                                              float4* __restrict__ ps4) {
    const int i = blockIdx.x * 256 + threadIdx.x;
    if (i < 10 * Ee / 4) ps4[i] = make_float4(0.f, 0.f, 0.f, 0.f);
    const float4* src;
    uint2* dst;
    int j = i;
    if (j < N_M1) { src = m1; dst = m1h; }
    else {
        j -= N_M1;
        if (j < N_F) { src = f; dst = fh; }
        else {
            j -= N_F;
            if (j < N_W) { src = wq; dst = wqh; }
            else { j -= N_W; if (j >= N_W) return; src = wk; dst = wkh; }
        }
    }
    float4 v = src[j];
    uint2 o;
    o.x = pack2(v.x, v.y);
    o.y = pack2(v.z, v.w);
    dst[j] = o;
}

__global__ void k_transpose(const float* __restrict__ src, float* __restrict__ dst) {
    __shared__ float tile[32][33];
    const int bx = blockIdx.x << 5, by = blockIdx.y << 5;
    #pragma unroll
    for (int j = 0; j < 4; j++)
        tile[threadIdx.y + j * 8][threadIdx.x] =
            src[(size_t)(by + threadIdx.y + j * 8) * 512 + bx + threadIdx.x];
    __syncthreads();
    #pragma unroll
    for (int j = 0; j < 4; j++)
        dst[(size_t)(bx + threadIdx.y + j * 8) * 512 + by + threadIdx.x] =
            tile[threadIdx.x][threadIdx.y + j * 8];
}

// BN + ELU; HOUT: write half, else fp32. Per-column constants hoisted
// (grid stride 2048*256 is a multiple of 128 -> c4 invariant per thread).
template<bool HOUT>
__global__ void __launch_bounds__(256) k_bn_elu(const float4* __restrict__ X,
                                                void* __restrict__ Y,
                                                const float4* __restrict__ sum4,
                                                const float4* __restrict__ sumsq4,
                                                const float4* __restrict__ g4,
                                                const float4* __restrict__ bt4) {
    const float invN = 1.f / (float)RR;
    const int total4 = RR * Ee / 4;
    const int i0 = blockIdx.x * blockDim.x + threadIdx.x;
    const int c4 = i0 & 127;
    float4 sm = sum4[c4], sq = sumsq4[c4], gg = g4[c4], bb = bt4[c4];
    float4 scv, shv;
    {
        float m, va;
        m = sm.x * invN; va = sq.x * invN - m * m;
        scv.x = gg.x * rsqrtf(va + EPSV); shv.x = bb.x - m * scv.x;
        m = sm.y * invN; va = sq.y * invN - m * m;
        scv.y = gg.y * rsqrtf(va + EPSV); shv.y = bb.y - m * scv.y;
        m = sm.z * invN; va = sq.z * invN - m * m;
        scv.z = gg.z * rsqrtf(va + EPSV); shv.z = bb.z - m * scv.z;
        m = sm.w * invN; va = sq.w * invN - m * m;
        scv.w = gg.w * rsqrtf(va + EPSV); shv.w = bb.w - m * scv.w;
    }
    for (int i = i0; i < total4; i += gridDim.x * blockDim.x) {
        float4 v = X[i];
        float4 o;
        o.x = elu_fast(v.x * scv.x + shv.x);
        o.y = elu_fast(v.y * scv.y + shv.y);
        o.z = elu_fast(v.z * scv.z + shv.z);
        o.w = elu_fast(v.w * scv.w + shv.w);
        if (HOUT) {
            uint2 u;
            u.x = pack2(o.x, o.y);
            u.y = pack2(o.z, o.w);
            ((uint2*)Y)[i] = u;
        } else {
            ((float4*)Y)[i] = o;
        }
    }
}

// Merged BN+ELU for q (y=0) and k (y=1); half output; hoisted constants.
__global__ void __launch_bounds__(256) k_bn_elu_qk(const float4* __restrict__ Xq,
                                                   uint2* __restrict__ Yq,
                                                   const float4* __restrict__ Xk,
                                                   uint2* __restrict__ Yk,
                                                   const float* __restrict__ stats,
                                                   const float4* __restrict__ gq,
                                                   const float4* __restrict__ bq,
                                                   const float4* __restrict__ gk,
                                                   const float4* __restrict__ bk) {
    const int z = blockIdx.y;
    const float4* X = z ? Xk : Xq;
    uint2* Y = z ? Yk : Yq;
    const float4* sum4 = (const float4*)(stats + (z ? 4 * Ee : 2 * Ee));
    const float4* sumsq4 = (const float4*)(stats + (z ? 5 * Ee : 3 * Ee));
    const float4* g4 = z ? gk : gq;
    const float4* bt4 = z ? bk : bq;
    const float invN = 1.f / (float)RR;
    const int total4 = RR * Ee / 4;
    const int i0 = blockIdx.x * blockDim.x + threadIdx.x;
    const int c4 = i0 & 127;
    float4 sm = sum4[c4], sq = sumsq4[c4], gg = g4[c4], bb = bt4[c4];
    float4 scv, shv;
    {
        float m, va;
        m = sm.x * invN; va = sq.x * invN - m * m;
        scv.x = gg.x * rsqrtf(va + EPSV); shv.x = bb.x - m * scv.x;
        m = sm.y * invN; va = sq.y * invN - m * m;
        scv.y = gg.y * rsqrtf(va + EPSV); shv.y = bb.y - m * scv.y;
        m = sm.z * invN; va = sq.z * invN - m * m;
        scv.z = gg.z * rsqrtf(va + EPSV); shv.z = bb.z - m * scv.z;
        m = sm.w * invN; va = sq.w * invN - m * m;
        scv.w = gg.w * rsqrtf(va + EPSV); shv.w = bb.w - m * scv.w;
    }
    for (int i = i0; i < total4; i += gridDim.x * blockDim.x) {
        float4 v = X[i];
        float4 o;
        o.x = elu_fast(v.x * scv.x + shv.x);
        o.y = elu_fast(v.y * scv.y + shv.y);
        o.z = elu_fast(v.z * scv.z + shv.z);
        o.w = elu_fast(v.w * scv.w + shv.w);
        uint2 u;
        u.x = pack2(o.x, o.y);
        u.y = pack2(o.z, o.w);
        Y[i] = u;
    }
}

// BN4 + softmax over q: WARP-PER-ROW (no barriers, no smem).
// Block = 256 thr = 8 warps = 8 rows; grid 2048 covers 16384 (b,k) rows.
// Lane j-th float4 at col 4*(j*32+lane) -> fully coalesced.
__global__ void __launch_bounds__(256) k_bn_softmax(const float* __restrict__ Wt,
                                                    __half* __restrict__ Wh,
                                                    const float* __restrict__ sum,
                                                    const float* __restrict__ sumsq,
                                                    const float* __restrict__ g4,
                                                    const float* __restrict__ b4) {
    const int warp = (blockIdx.x << 3) + (threadIdx.x >> 5);  // row (b*512+k)
    const int lane = threadIdx.x & 31;
    const int k = warp & 511;
    const float* row = Wt + ((size_t)warp << 9);
    const float invN = 1.f / (float)RR;
    const float mean = sum[k] * invN;
    const float var = sumsq[k] * invN - mean * mean;
    const float sc = g4[k] * rsqrtf(var + EPSV);
    const float shf = b4[k] - mean * sc;

    float x[4][4];
    float mx = -INFINITY;
    #pragma unroll
    for (int j = 0; j < 4; j++) {
        float4 v = *(const float4*)(row + 4 * (j * 32 + lane));
        x[j][0] = v.x * sc + shf;
        x[j][1] = v.y * sc + shf;
        x[j][2] = v.z * sc + shf;
        x[j][3] = v.w * sc + shf;
        mx = fmaxf(mx, fmaxf(fmaxf(x[j][0], x[j][1]), fmaxf(x[j][2], x[j][3])));
    }
    #pragma unroll
    for (int o = 16; o > 0; o >>= 1) mx = fmaxf(mx, __shfl_xor_sync(0xffffffffu, mx, o));

    float tot = 0.f;
    #pragma unroll
    for (int j = 0; j < 4; j++) {
        #pragma unroll
        for (int e = 0; e < 4; e++) {
            x[j][e] = __expf(x[j][e] - mx);
            tot += x[j][e];
        }
    }
    #pragma unroll
    for (int o = 16; o > 0; o >>= 1) tot += __shfl_xor_sync(0xffffffffu, tot, o);
    const float inv = 1.f / tot;

    __half* orow = Wh + ((size_t)warp << 9);
    #pragma unroll
    for (int j = 0; j < 4; j++) {
        uint2 u;
        u.x = pack2(x[j][0] * inv, x[j][1] * inv);
        u.y = pack2(x[j][2] * inv, x[j][3] * inv);
        *(uint2*)(orow + 4 * (j * 32 + lane)) = u;
    }
}

// ---------------------------------------------------------------------------
// fp16 GEMMs (identical to passing R10/R13/R15 code)
// ---------------------------------------------------------------------------

// GEMM1: C = unfold(m1h) @ fh + kb. A gathered m-major, B k-major. Col stats.
__global__ void __launch_bounds__(128) k_gemm1(const __half* __restrict__ Ah,
                                               const __half* __restrict__ Bh,
                                               const float* __restrict__ kb,
                                               float* __restrict__ C,
                                               float* __restrict__ ssum,
                                               float* __restrict__ ssq) {
    __shared__ uint32_t As[2][16][PADW];
    __shared__ uint32_t Bs[2][16][PADW];
    float c[4][8][4] = {{{0.f}}};
    const int tid = threadIdx.x;
    const int lane = tid & 31, wid = tid >> 5;
    const int g = lane >> 2, t = lane & 3;
    const int wm = (wid & 1) << 6, wn = (wid >> 1) << 6;
    const int br = blockIdx.y << 7, bc = blockIdx.x << 7;
    const int kpb = tid >> 5, c0 = (tid & 31) << 2;

    const int row = br + tid;
    const int bA = row >> 9, lA = row & 511;

    uint4 av[4];
    uint2 bx[4], by[4];
    {
        const int sl = lA - 2;
        if ((unsigned)sl < 512u)
            ld_mmaj(av, Ah + (((size_t)(bA << 9) + sl) << 9));
        else
            av[0] = av[1] = av[2] = av[3] = make_uint4(0, 0, 0, 0);
        ld_kmaj(bx, by, Bh, Ee, 0, kpb, bc + c0);
    }
    st_mmaj(As[0], tid, av);
    st_kmaj(Bs[0], kpb, c0, bx, by);

    const int nIter = KE / 32;
    for (int i = 0; i < nIter; i++) {
        const int buf = i & 1, nb = buf ^ 1;
        __syncthreads();
        const int k1 = (i + 1) << 5;
        if (i + 1 < nIter) {
            const int sl = lA + (k1 >> 9) - 2;
            if ((unsigned)sl < 512u)
                ld_mmaj(av, Ah + (((size_t)(bA << 9) + sl) << 9) + (k1 & 511));
            else
                av[0] = av[1] = av[2] = av[3] = make_uint4(0, 0, 0, 0);
            ld_kmaj(bx, by, Bh, Ee, k1, kpb, bc + c0);
        }
        mma_core64h(As[buf], Bs[buf], c, g, t, wm, wn);
        if (i + 1 < nIter) {
            st_mmaj(As[nb], tid, av);
            st_kmaj(Bs[nb], kpb, c0, bx, by);
        }
    }

    float cs[16] = {0.f}, cq[16] = {0.f};
    #pragma unroll
    for (int mt = 0; mt < 4; mt++)
        #pragma unroll
        for (int i = 0; i < 2; i++) {
            const int rowo = br + wm + mt * 16 + g + 8 * i;
            const int l = rowo & 511;
            #pragma unroll
            for (int nt = 0; nt < 8; nt++) {
                const int col = bc + wn + nt * 8 + 2 * t;
                float2 bvv = *(const float2*)(kb + (size_t)l * 512 + col);
                float2 v;
                v.x = c[mt][nt][2 * i + 0] + bvv.x;
                v.y = c[mt][nt][2 * i + 1] + bvv.y;
                cs[nt * 2 + 0] += v.x; cq[nt * 2 + 0] += v.x * v.x;
                cs[nt * 2 + 1] += v.y; cq[nt * 2 + 1] += v.y * v.y;
                *(float2*)(C + (size_t)rowo * 512 + col) = v;
            }
        }
    colstats_epilogue(ssum, ssq, cs, cq, g, t, bc + wn);
}

// Fused NN GEMMs (z=0: q2 = l@wq + qb ; z=1: k2 = l@wk + kb). Col stats fused.
__global__ void __launch_bounds__(128) k_gemm_nn(const __half* __restrict__ Ah,
                                                 const __half* __restrict__ Bqh,
                                                 const __half* __restrict__ Bkh,
                                                 const float* __restrict__ biasq,
                                                 const float* __restrict__ biask,
                                                 float* __restrict__ Cq,
                                                 float* __restrict__ Ck,
                                                 float* __restrict__ stats) {
    const __half* Bh = blockIdx.z ? Bkh : Bqh;
    const float* bias = blockIdx.z ? biask : biasq;
    float* C = blockIdx.z ? Ck : Cq;
    float* ssum = stats + (blockIdx.z ? 4 * Ee : 2 * Ee);
    float* ssq = ssum + Ee;
    __shared__ uint32_t As[2][16][PADW];
    __shared__ uint32_t Bs[2][16][PADW];
    float c[4][8][4] = {{{0.f}}};
    const int tid = threadIdx.x;
    const int lane = tid & 31, wid = tid >> 5;
    const int g = lane >> 2, t = lane & 3;
    const int wm = (wid & 1) << 6, wn = (wid >> 1) << 6;
    const int br = blockIdx.y << 7, bc = blockIdx.x << 7;
    const int kpb = tid >> 5, c0 = (tid & 31) << 2;

    uint4 av[4];
    uint2 bx[4], by[4];
    ld_mmaj(av, Ah + (size_t)(br + tid) * 512);
    ld_kmaj(bx, by, Bh, 512, 0, kpb, bc + c0);
    st_mmaj(As[0], tid, av);
    st_kmaj(Bs[0], kpb, c0, bx, by);

    const int nIter = 16;
    for (int i = 0; i < nIter; i++) {
        const int buf = i & 1, nb = buf ^ 1;
        __syncthreads();
        const int k1 = (i + 1) << 5;
        if (i + 1 < nIter) {
            ld_mmaj(av, Ah + (size_t)(br + tid) * 512 + k1);
            ld_kmaj(bx, by, Bh, 512, k1, kpb, bc + c0);
        }
        mma_core64h(As[buf], Bs[buf], c, g, t, wm, wn);
        if (i + 1 < nIter) {
            st_mmaj(As[nb], tid, av);
            st_kmaj(Bs[nb], kpb, c0, bx, by);
        }
    }

    float cs[16] = {0.f}, cq[16] = {0.f};
    #pragma unroll
    for (int mt = 0; mt < 4; mt++)
        #pragma unroll
        for (int i = 0; i < 2; i++) {
            const int rowo = br + wm + mt * 16 + g + 8 * i;
            const int l = rowo & 511;
            #pragma unroll
            for (int nt = 0; nt < 8; nt++) {
                const int col = bc + wn + nt * 8 + 2 * t;
                float2 bvv = *(const float2*)(bias + (size_t)l * 512 + col);
                float2 v;
                v.x = c[mt][nt][2 * i + 0] + bvv.x;
                v.y = c[mt][nt][2 * i + 1] + bvv.y;
                cs[nt * 2 + 0] += v.x; cq[nt * 2 + 0] += v.x * v.x;
                cs[nt * 2 + 1] += v.y; cq[nt * 2 + 1] += v.y * v.y;
                *(float2*)(C + (size_t)rowo * 512 + col) = v;
            }
        }
    colstats_epilogue(ssum, ssq, cs, cq, g, t, bc + wn);
}

// Batched NT: C[k,q] = sum_e k2[k,e]*q2[q,e] + wbT. Both m-major. Row stats.
__global__ void __launch_bounds__(128) k_gemm_nt(const __half* __restrict__ Ain,
                                                 const __half* __restrict__ Bin,
                                                 const float* __restrict__ wbT,
                                                 float* __restrict__ Cout,
                                                 float* __restrict__ rsum,
                                                 float* __restrict__ rsq) {
    const int bz = blockIdx.z;
    const __half* A = Ain + (size_t)bz * Ll * Ee;
    const __half* Bm = Bin + (size_t)bz * Ll * Ee;
    float* C = Cout + (size_t)bz * Ll * Ll;
    __shared__ uint32_t As[2][16][PADW];
    __shared__ uint32_t Bs[2][16][PADW];
    float c[4][8][4] = {{{0.f}}};
    const int tid = threadIdx.x;
    const int lane = tid & 31, wid = tid >> 5;
    const int g = lane >> 2, t = lane & 3;
    const int wm = (wid & 1) << 6, wn = (wid >> 1) << 6;
    const int br = blockIdx.y << 7, bc = blockIdx.x << 7;

    uint4 av[4], bv[4];
    ld_mmaj(av, A + (size_t)(br + tid) * 512);
    ld_mmaj(bv, Bm + (size_t)(bc + tid) * 512);
    st_mmaj(As[0], tid, av);
    st_mmaj(Bs[0], tid, bv);

    const int nIter = 16;
    for (int i = 0; i < nIter; i++) {
        const int buf = i & 1, nb = buf ^ 1;
        __syncthreads();
        const int k1 = (i + 1) << 5;
        if (i + 1 < nIter) {
            ld_mmaj(av, A + (size_t)(br + tid) * 512 + k1);
            ld_mmaj(bv, Bm + (size_t)(bc + tid) * 512 + k1);
        }
        mma_core64h(As[buf], Bs[buf], c, g, t, wm, wn);
        if (i + 1 < nIter) {
            st_mmaj(As[nb], tid, av);
            st_mmaj(Bs[nb], tid, bv);
        }
    }

    float rs[8] = {0.f}, rq[8] = {0.f};
    #pragma unroll
    for (int mt = 0; mt < 4; mt++)
        #pragma unroll
        for (int i = 0; i < 2; i++) {
            const int rowo = br + wm + mt * 16 + g + 8 * i;
            #pragma unroll
            for (int nt = 0; nt < 8; nt++) {
                const int col = bc + wn + nt * 8 + 2 * t;
                float2 bv2 = *(const float2*)(wbT + (size_t)rowo * 512 + col);
                float2 v;
                v.x = c[mt][nt][2 * i + 0] + bv2.x;
                v.y = c[mt][nt][2 * i + 1] + bv2.y;
                rs[mt * 2 + i] += v.x + v.y;
                rq[mt * 2 + i] += v.x * v.x + v.y * v.y;
                *(float2*)(C + (size_t)rowo * 512 + col) = v;
            }
        }
    #pragma unroll
    for (int x = 0; x < 8; x++) {
        float s = rs[x], q = rq[x];
        s += __shfl_xor_sync(0xffffffffu, s, 1); q += __shfl_xor_sync(0xffffffffu, q, 1);
        s += __shfl_xor_sync(0xffffffffu, s, 2); q += __shfl_xor_sync(0xffffffffu, q, 2);
        if (t == 0) {
            const int rowo = br + wm + (x >> 1) * 16 + g + 8 * (x & 1);
            atomicAdd(&rsum[rowo], s);
            atomicAdd(&rsq[rowo], q);
        }
    }
}

// Batched TN: C[q,e] = sum_k wh[k,q]*lh[k,e]. Both k-major. Col stats fused.
__global__ void __launch_bounds__(128) k_gemm_tn(const __half* __restrict__ Ain,
                                                 const __half* __restrict__ Bin,
                                                 float* __restrict__ Cout,
                                                 float* __restrict__ ssum,
                                                 float* __restrict__ ssq) {
    const int bz = blockIdx.z;
    const __half* A = Ain + (size_t)bz * Ll * Ll;
    const __half* Bm = Bin + (size_t)bz * Ll * Ee;
    float* C = Cout + (size_t)bz * Ll * Ee;
    __shared__ uint32_t As[2][16][PADW];
    __shared__ uint32_t Bs[2][16][PADW];
    float c[4][8][4] = {{{0.f}}};
    const int tid = threadIdx.x;
    const int lane = tid & 31, wid = tid >> 5;
    const int g = lane >> 2, t = lane & 3;
    const int wm = (wid & 1) << 6, wn = (wid >> 1) << 6;
    const int br = blockIdx.y << 7, bc = blockIdx.x << 7;
    const int kpb = tid >> 5, c0 = (tid & 31) << 2;

    uint2 ax[4], ay[4], bx[4], by[4];
    ld_kmaj(ax, ay, A, 512, 0, kpb, br + c0);
    ld_kmaj(bx, by, Bm, 512, 0, kpb, bc + c0);
    st_kmaj(As[0], kpb, c0, ax, ay);
    st_kmaj(Bs[0], kpb, c0, bx, by);

    const int nIter = 16;
    for (int i = 0; i < nIter; i++) {
        const int buf = i & 1, nb = buf ^ 1;
        __syncthreads();
        const int k1 = (i + 1) << 5;
        if (i + 1 < nIter) {
            ld_kmaj(ax, ay, A, 512, k1, kpb, br + c0);
            ld_kmaj(bx, by, Bm, 512, k1, kpb, bc + c0);
        }
        mma_core64h(As[buf], Bs[buf], c, g, t, wm, wn);
        if (i + 1 < nIter) {
            st_kmaj(As[nb], kpb, c0, ax, ay);
            st_kmaj(Bs[nb], kpb, c0, bx, by);
        }
    }

    float cs[16] = {0.f}, cq[16] = {0.f};
    #pragma unroll
    for (int mt = 0; mt < 4; mt++)
        #pragma unroll
        for (int i = 0; i < 2; i++) {
            const int rowo = br + wm + mt * 16 + g + 8 * i;
            #pragma unroll
            for (int nt = 0; nt < 8; nt++) {
                const int col = bc + wn + nt * 8 + 2 * t;
                float2 v;
                v.x = c[mt][nt][2 * i + 0];
                v.y = c[mt][nt][2 * i + 1];
                cs[nt * 2 + 0] += v.x; cq[nt * 2 + 0] += v.x * v.x;
                cs[nt * 2 + 1] += v.y; cq[nt * 2 + 1] += v.y * v.y;
                *(float2*)(C + (size_t)rowo * 512 + col) = v;
            }
        }
    colstats_epilogue(ssum, ssq, cs, cq, g, t, bc + wn);
}

extern "C" void kernel_launch(void* const* d_in, const int* in_sizes, int n_in,
                              void* d_out, int out_size) {
    const float* m1 = (const float*)d_in[0];
    const float* f  = (const float*)d_in[1];
    const float* wq = (const float*)d_in[2];
    const float* wk = (const float*)d_in[3];
    const float* qb = (const float*)d_in[4];
    const float* kb = (const float*)d_in[5];
    const float* wb = (const float*)d_in[6];
    const float* g1 = (const float*)d_in[7];  const float* b1 = (const float*)d_in[8];
    const float* g2 = (const float*)d_in[9];  const float* b2 = (const float*)d_in[10];
    const float* g3 = (const float*)d_in[11]; const float* b3 = (const float*)d_in[12];
    const float* g4 = (const float*)d_in[13]; const float* b4 = (const float*)d_in[14];
    const float* g5 = (const float*)d_in[15]; const float* b5 = (const float*)d_in[16];

    float *pl, *pq, *pk, *pw, *po, *ps, *pwbT;
    __half *pm1h, *pfh, *pwqh, *pwkh, *plh, *pqh, *pkh, *pwh;
    cudaGetSymbolAddress((void**)&pl, g_l);
    cudaGetSymbolAddress((void**)&pq, g_q);
    cudaGetSymbolAddress((void**)&pk, g_k);
    cudaGetSymbolAddress((void**)&pw, g_w);
    cudaGetSymbolAddress((void**)&po, g_o);
    cudaGetSymbolAddress((void**)&ps, g_s);
    cudaGetSymbolAddress((void**)&pwbT, g_wbT);
    cudaGetSymbolAddress((void**)&pm1h, g_m1h);
    cudaGetSymbolAddress((void**)&pfh, g_fh);
    cudaGetSymbolAddress((void**)&pwqh, g_wqh);
    cudaGetSymbolAddress((void**)&pwkh, g_wkh);
    cudaGetSymbolAddress((void**)&plh, g_lh);
    cudaGetSymbolAddress((void**)&pqh, g_qh);
    cudaGetSymbolAddress((void**)&pkh, g_kh);
    cudaGetSymbolAddress((void**)&pwh, g_wh);

    const int T = 256, TG = 128;

    k_prep<<<(N_PREP + 255) / 256, T>>>((const float4*)m1, (uint2*)pm1h,
                                        (const float4*)f, (uint2*)pfh,
                                        (const float4*)wq, (uint2*)pwqh,
                                        (const float4*)wk, (uint2*)pwkh,
                                        (float4*)ps);
    k_transpose<<<dim3(16, 16), dim3(32, 8)>>>(wb, pwbT);

    // 1) l_pre = unfold(m1) @ f + kb ; BN1+ELU -> half
    k_gemm1<<<dim3(4, 128), TG>>>(pm1h, pfh, kb, pl, ps + 0 * Ee, ps + 1 * Ee);
    k_bn_elu<true><<<2048, T>>>((const float4*)pl, plh,
                                (const float4*)(ps + 0 * Ee), (const float4*)(ps + 1 * Ee),
                                (const float4*)g1, (const float4*)b1);

    // 2) q2 / k2 ; merged BN+ELU -> half
    k_gemm_nn<<<dim3(4, 128, 2), TG>>>(plh, pwqh, pwkh, qb, kb, pq, pk, ps);
    k_bn_elu_qk<<<dim3(2048, 2), T>>>((const float4*)pq, (uint2*)pqh,
                                      (const float4*)pk, (uint2*)pkh, ps,
                                      (const float4*)g2, (const float4*)b2,
                                      (const float4*)g3, (const float4*)b3);

    // 3) wT = k2 @ q2^T + wbT ; BN4 + softmax (warp-per-row) -> half
    k_gemm_nt<<<dim3(4, 4, 32), TG>>>(pkh, pqh, pwbT, pw, ps + 8 * Ee, ps + 9 * Ee);
    k_bn_softmax<<<2048, T>>>(pw, pwh, ps + 8 * Ee, ps + 9 * Ee, g4, b4);

    // 4) out = wT^T @ l ; BN5 + ELU -> d_out (fp32)
    k_gemm_tn<<<dim3(4, 4, 32), TG>>>(pwh, plh, po, ps + 6 * Ee, ps + 7 * Ee);
    k_bn_elu<false><<<2048, T>>>((const float4*)po, d_out,
                                 (const float4*)(ps + 6 * Ee), (const float4*)(ps + 7 * Ee),
                                 (const float4*)g5, (const float4*)b5);
}

// round 17
// speedup vs baseline: 1.2617x; 1.0142x over previous
#include <cuda_runtime.h>
#include <cuda_fp16.h>
#include <math.h>
#include <stdint.h>

#define Bb 32
#define Ll 512
#define Ee 512
#define RR (Bb*Ll)
#define KE (5*Ee)
#define EPSV 1e-3f
#define PADW 136

// fp32 scratch (pre-BN activations for exact stats)
__device__ float g_l[RR*Ee];
__device__ float g_q[RR*Ee];
__device__ float g_k[RR*Ee];
__device__ float g_w[Bb*Ll*Ll];     // wT[b,k,q] pre-BN fp32
__device__ float g_o[RR*Ee];
__device__ float g_wbT[Ll*Ll];
__device__ float g_s[10*Ee];
// fp16 operands
__device__ __half g_m1h[RR*Ee];
__device__ __half g_fh[KE*Ee];
__device__ __half g_wqh[Ee*Ee];
__device__ __half g_wkh[Ee*Ee];
__device__ __half g_lh[RR*Ee];
__device__ __half g_qh[RR*Ee];
__device__ __half g_kh[RR*Ee];
__device__ __half g_wh[Bb*Ll*Ll];

__device__ __forceinline__ uint32_t pack2(float a, float b) {
    __half2 h = __floats2half2_rn(a, b);
    return *(uint32_t*)&h;
}
__device__ __forceinline__ float elu_fast(float y) {
    return y > 0.f ? y : (__expf(y) - 1.f);
}

// ---------------------------------------------------------------------------
// fp16 mma core: 64x64 warp tile over [16][PADW] kpair-word tiles, BK=32.
// ---------------------------------------------------------------------------
__device__ __forceinline__ void mma_core64h(const uint32_t (*As)[PADW],
                                            const uint32_t (*Bs)[PADW],
                                            float c[4][8][4],
                                            int g, int t, int wm, int wn) {
    #pragma unroll
    for (int ks = 0; ks < 2; ks++) {
        const int kb = ks * 8;
        uint32_t a[4][4], b[8][2];
        #pragma unroll
        for (int mt = 0; mt < 4; mt++) {
            const int m = wm + mt * 16 + g;
            a[mt][0] = As[kb + t][m];
            a[mt][1] = As[kb + t][m + 8];
            a[mt][2] = As[kb + t + 4][m];
            a[mt][3] = As[kb + t + 4][m + 8];
        }
        #pragma unroll
        for (int nt = 0; nt < 8; nt++) {
            const int n = wn + nt * 8 + g;
            b[nt][0] = Bs[kb + t][n];
            b[nt][1] = Bs[kb + t + 4][n];
        }
        #pragma unroll
        for (int mt = 0; mt < 4; mt++)
            #pragma unroll
            for (int nt = 0; nt < 8; nt++)
                asm volatile(
                    "mma.sync.aligned.m16n8k16.row.col.f32.f16.f16.f32 "
                    "{%0,%1,%2,%3},{%4,%5,%6,%7},{%8,%9},{%0,%1,%2,%3};"
                    : "+f"(c[mt][nt][0]), "+f"(c[mt][nt][1]),
                      "+f"(c[mt][nt][2]), "+f"(c[mt][nt][3])
                    : "r"(a[mt][0]), "r"(a[mt][1]), "r"(a[mt][2]), "r"(a[mt][3]),
                      "r"(b[nt][0]), "r"(b[nt][1]));
    }
}

// m-major staging: thread col m = tid, 32 k-contig halves = 4 x uint4.
__device__ __forceinline__ void ld_mmaj(uint4 v[4], const __half* src) {
    const uint4* p = (const uint4*)src;
    v[0] = p[0]; v[1] = p[1]; v[2] = p[2]; v[3] = p[3];
}
__device__ __forceinline__ void st_mmaj(uint32_t (*S)[PADW], int m, const uint4 v[4]) {
    #pragma unroll
    for (int u = 0; u < 4; u++) {
        S[4*u + 0][m] = v[u].x;
        S[4*u + 1][m] = v[u].y;
        S[4*u + 2][m] = v[u].z;
        S[4*u + 3][m] = v[u].w;
    }
}
// k-major staging: thread covers colquad c0 = 4*(tid&31), kp = (tid>>5)+4j.
__device__ __forceinline__ void ld_kmaj(uint2 x[4], uint2 y[4], const __half* B,
                                        int ld, int k0, int kpb, int gcol) {
    #pragma unroll
    for (int j = 0; j < 4; j++) {
        const __half* r = B + (size_t)(k0 + 2 * (kpb + 4 * j)) * ld + gcol;
        x[j] = *(const uint2*)r;
        y[j] = *(const uint2*)(r + ld);
    }
}
__device__ __forceinline__ void st_kmaj(uint32_t (*S)[PADW], int kpb, int c0,
                                        const uint2 x[4], const uint2 y[4]) {
    #pragma unroll
    for (int j = 0; j < 4; j++) {
        const int kp = kpb + 4 * j;
        uint4 w;
        w.x = __byte_perm(x[j].x, y[j].x, 0x5410);
        w.y = __byte_perm(x[j].x, y[j].x, 0x7632);
        w.z = __byte_perm(x[j].y, y[j].y, 0x5410);
        w.w = __byte_perm(x[j].y, y[j].y, 0x7632);
        *(uint4*)&S[kp][c0] = w;
    }
}

__device__ __forceinline__ void colstats_epilogue(float* __restrict__ sum,
                                                  float* __restrict__ sumsq,
                                                  const float cs[16], const float cq[16],
                                                  int g, int t, int bcwn) {
    #pragma unroll
    for (int x = 0; x < 16; x++) {
        float s = cs[x], q = cq[x];
        s += __shfl_xor_sync(0xffffffffu, s, 4);  q += __shfl_xor_sync(0xffffffffu, q, 4);
        s += __shfl_xor_sync(0xffffffffu, s, 8);  q += __shfl_xor_sync(0xffffffffu, q, 8);
        s += __shfl_xor_sync(0xffffffffu, s, 16); q += __shfl_xor_sync(0xffffffffu, q, 16);
        if (g == 0) {
            const int col = bcwn + (x >> 1) * 8 + 2 * t + (x & 1);
            atomicAdd(&sum[col], s);
            atomicAdd(&sumsq[col], q);
        }
    }
}

// Fused pre-pass: zero stats + fp32->fp16 for m1/f/wq/wk (4 strided elems per
// thread; PREP_MAIN*1024 == N_PREP exactly) + wb transpose (last 256 blocks).
#define N_M1 (RR*Ee/4)
#define N_F  (KE*Ee/4)
#define N_W  (Ee*Ee/4)
#define N_PREP (N_M1 + N_F + 2*N_W)
#define PREP_MAIN (N_PREP / 1024)
__global__ void __launch_bounds__(256) k_prep(const float4* __restrict__ m1,
                                              uint2* __restrict__ m1h,
                                              const float4* __restrict__ f,
                                              uint2* __restrict__ fh,
                                              const float4* __restrict__ wq,
                                              uint2* __restrict__ wqh,
                                              const float4* __restrict__ wk,
                                              uint2* __restrict__ wkh,
                                              float4* __restrict__ ps4,
                                              const float* __restrict__ wb,
                                              float* __restrict__ wbT) {
    __shared__ float tile[32][33];
    if (blockIdx.x < PREP_MAIN) {
        const int tidg = blockIdx.x * 256 + threadIdx.x;
        const int stride = PREP_MAIN * 256;
        if (tidg < 10 * Ee / 4) ps4[tidg] = make_float4(0.f, 0.f, 0.f, 0.f);
        float4 v[4];
        #pragma unroll
        for (int s = 0; s < 4; s++) {
            const int j = tidg + s * stride;
            const float4* src;
            int jj = j;
            if (jj < N_M1) src = m1;
            else {
                jj -= N_M1;
                if (jj < N_F) src = f;
                else { jj -= N_F; src = (jj < N_W) ? wq : wk; if (jj >= N_W) jj -= N_W; }
            }
            v[s] = src[jj];
        }
        #pragma unroll
        for (int s = 0; s < 4; s++) {
            const int j = tidg + s * stride;
            uint2* dst;
            int jj = j;
            if (jj < N_M1) dst = m1h;
            else {
                jj -= N_M1;
                if (jj < N_F) dst = fh;
                else { jj -= N_F; dst = (jj < N_W) ? wqh : wkh; if (jj >= N_W) jj -= N_W; }
            }
            uint2 o;
            o.x = pack2(v[s].x, v[s].y);
            o.y = pack2(v[s].z, v[s].w);
            dst[jj] = o;
        }
    } else {
        const int bid2 = blockIdx.x - PREP_MAIN;   // 0..255
        const int tx = threadIdx.x & 31, ty = threadIdx.x >> 5;
        const int bx = (bid2 & 15) << 5, by = (bid2 >> 4) << 5;
        #pragma unroll
        for (int j = 0; j < 4; j++)
            tile[ty + j * 8][tx] =
                wb[(size_t)(by + ty + j * 8) * 512 + bx + tx];
        __syncthreads();
        #pragma unroll
        for (int j = 0; j < 4; j++)
            wbT[(size_t)(bx + ty + j * 8) * 512 + by + tx] =
                tile[tx][ty + j * 8];
    }
}

// BN + ELU; HOUT: write half, else fp32. Per-column constants hoisted;
// fixed 4-iteration stride loop (2048*256*4 == total exactly), batched loads.
template<bool HOUT>
__global__ void __launch_bounds__(256) k_bn_elu(const float4* __restrict__ X,
                                                void* __restrict__ Y,
                                                const float4* __restrict__ sum4,
                                                const float4* __restrict__ sumsq4,
                                                const float4* __restrict__ g4,
                                                const float4* __restrict__ bt4) {
    const float invN = 1.f / (float)RR;
    const int stride = 2048 * 256;
    const int i0 = blockIdx.x * 256 + threadIdx.x;
    const int c4 = i0 & 127;
    float4 sm = sum4[c4], sq = sumsq4[c4], gg = g4[c4], bb = bt4[c4];
    float4 scv, shv;
    {
        float m, va;
        m = sm.x * invN; va = sq.x * invN - m * m;
        scv.x = gg.x * rsqrtf(va + EPSV); shv.x = bb.x - m * scv.x;
        m = sm.y * invN; va = sq.y * invN - m * m;
        scv.y = gg.y * rsqrtf(va + EPSV); shv.y = bb.y - m * scv.y;
        m = sm.z * invN; va = sq.z * invN - m * m;
        scv.z = gg.z * rsqrtf(va + EPSV); shv.z = bb.z - m * scv.z;
        m = sm.w * invN; va = sq.w * invN - m * m;
        scv.w = gg.w * rsqrtf(va + EPSV); shv.w = bb.w - m * scv.w;
    }
    float4 v[4];
    #pragma unroll
    for (int s = 0; s < 4; s++) v[s] = X[i0 + s * stride];
    #pragma unroll
    for (int s = 0; s < 4; s++) {
        float4 o;
        o.x = elu_fast(v[s].x * scv.x + shv.x);
        o.y = elu_fast(v[s].y * scv.y + shv.y);
        o.z = elu_fast(v[s].z * scv.z + shv.z);
        o.w = elu_fast(v[s].w * scv.w + shv.w);
        if (HOUT) {
            uint2 u;
            u.x = pack2(o.x, o.y);
            u.y = pack2(o.z, o.w);
            ((uint2*)Y)[i0 + s * stride] = u;
        } else {
            ((float4*)Y)[i0 + s * stride] = o;
        }
    }
}

// Merged BN+ELU for q (y=0) and k (y=1); half output; hoisted; batched loads.
__global__ void __launch_bounds__(256) k_bn_elu_qk(const float4* __restrict__ Xq,
                                                   uint2* __restrict__ Yq,
                                                   const float4* __restrict__ Xk,
                                                   uint2* __restrict__ Yk,
                                                   const float* __restrict__ stats,
                                                   const float4* __restrict__ gq,
                                                   const float4* __restrict__ bq,
                                                   const float4* __restrict__ gk,
                                                   const float4* __restrict__ bk) {
    const int z = blockIdx.y;
    const float4* X = z ? Xk : Xq;
    uint2* Y = z ? Yk : Yq;
    const float4* sum4 = (const float4*)(stats + (z ? 4 * Ee : 2 * Ee));
    const float4* sumsq4 = (const float4*)(stats + (z ? 5 * Ee : 3 * Ee));
    const float4* g4 = z ? gk : gq;
    const float4* bt4 = z ? bk : bq;
    const float invN = 1.f / (float)RR;
    const int stride = 2048 * 256;
    const int i0 = blockIdx.x * 256 + threadIdx.x;
    const int c4 = i0 & 127;
    float4 sm = sum4[c4], sq = sumsq4[c4], gg = g4[c4], bb = bt4[c4];
    float4 scv, shv;
    {
        float m, va;
        m = sm.x * invN; va = sq.x * invN - m * m;
        scv.x = gg.x * rsqrtf(va + EPSV); shv.x = bb.x - m * scv.x;
        m = sm.y * invN; va = sq.y * invN - m * m;
        scv.y = gg.y * rsqrtf(va + EPSV); shv.y = bb.y - m * scv.y;
        m = sm.z * invN; va = sq.z * invN - m * m;
        scv.z = gg.z * rsqrtf(va + EPSV); shv.z = bb.z - m * scv.z;
        m = sm.w * invN; va = sq.w * invN - m * m;
        scv.w = gg.w * rsqrtf(va + EPSV); shv.w = bb.w - m * scv.w;
    }
    float4 v[4];
    #pragma unroll
    for (int s = 0; s < 4; s++) v[s] = X[i0 + s * stride];
    #pragma unroll
    for (int s = 0; s < 4; s++) {
        float4 o;
        o.x = elu_fast(v[s].x * scv.x + shv.x);
        o.y = elu_fast(v[s].y * scv.y + shv.y);
        o.z = elu_fast(v[s].z * scv.z + shv.z);
        o.w = elu_fast(v[s].w * scv.w + shv.w);
        uint2 u;
        u.x = pack2(o.x, o.y);
        u.y = pack2(o.z, o.w);
        Y[i0 + s * stride] = u;
    }
}

// BN4 + softmax over q: WARP-PER-ROW (no barriers, no smem).
__global__ void __launch_bounds__(256) k_bn_softmax(const float* __restrict__ Wt,
                                                    __half* __restrict__ Wh,
                                                    const float* __restrict__ sum,
                                                    const float* __restrict__ sumsq,
                                                    const float* __restrict__ g4,
                                                    const float* __restrict__ b4) {
    const int warp = (blockIdx.x << 3) + (threadIdx.x >> 5);  // row (b*512+k)
    const int lane = threadIdx.x & 31;
    const int k = warp & 511;
    const float* row = Wt + ((size_t)warp << 9);
    const float invN = 1.f / (float)RR;
    const float mean = sum[k] * invN;
    const float var = sumsq[k] * invN - mean * mean;
    const float sc = g4[k] * rsqrtf(var + EPSV);
    const float shf = b4[k] - mean * sc;

    float x[4][4];
    float mx = -INFINITY;
    #pragma unroll
    for (int j = 0; j < 4; j++) {
        float4 v = *(const float4*)(row + 4 * (j * 32 + lane));
        x[j][0] = v.x * sc + shf;
        x[j][1] = v.y * sc + shf;
        x[j][2] = v.z * sc + shf;
        x[j][3] = v.w * sc + shf;
        mx = fmaxf(mx, fmaxf(fmaxf(x[j][0], x[j][1]), fmaxf(x[j][2], x[j][3])));
    }
    #pragma unroll
    for (int o = 16; o > 0; o >>= 1) mx = fmaxf(mx, __shfl_xor_sync(0xffffffffu, mx, o));

    float tot = 0.f;
    #pragma unroll
    for (int j = 0; j < 4; j++) {
        #pragma unroll
        for (int e = 0; e < 4; e++) {
            x[j][e] = __expf(x[j][e] - mx);
            tot += x[j][e];
        }
    }
    #pragma unroll
    for (int o = 16; o > 0; o >>= 1) tot += __shfl_xor_sync(0xffffffffu, tot, o);
    const float inv = 1.f / tot;

    __half* orow = Wh + ((size_t)warp << 9);
    #pragma unroll
    for (int j = 0; j < 4; j++) {
        uint2 u;
        u.x = pack2(x[j][0] * inv, x[j][1] * inv);
        u.y = pack2(x[j][2] * inv, x[j][3] * inv);
        *(uint2*)(orow + 4 * (j * 32 + lane)) = u;
    }
}

// ---------------------------------------------------------------------------
// fp16 GEMMs (identical to passing R10..R16 code)
// ---------------------------------------------------------------------------

// GEMM1: C = unfold(m1h) @ fh + kb. A gathered m-major, B k-major. Col stats.
__global__ void __launch_bounds__(128) k_gemm1(const __half* __restrict__ Ah,
                                               const __half* __restrict__ Bh,
                                               const float* __restrict__ kb,
                                               float* __restrict__ C,
                                               float* __restrict__ ssum,
                                               float* __restrict__ ssq) {
    __shared__ uint32_t As[2][16][PADW];
    __shared__ uint32_t Bs[2][16][PADW];
    float c[4][8][4] = {{{0.f}}};
    const int tid = threadIdx.x;
    const int lane = tid & 31, wid = tid >> 5;
    const int g = lane >> 2, t = lane & 3;
    const int wm = (wid & 1) << 6, wn = (wid >> 1) << 6;
    const int br = blockIdx.y << 7, bc = blockIdx.x << 7;
    const int kpb = tid >> 5, c0 = (tid & 31) << 2;

    const int row = br + tid;
    const int bA = row >> 9, lA = row & 511;

    uint4 av[4];
    uint2 bx[4], by[4];
    {
        const int sl = lA - 2;
        if ((unsigned)sl < 512u)
            ld_mmaj(av, Ah + (((size_t)(bA << 9) + sl) << 9));
        else
            av[0] = av[1] = av[2] = av[3] = make_uint4(0, 0, 0, 0);
        ld_kmaj(bx, by, Bh, Ee, 0, kpb, bc + c0);
    }
    st_mmaj(As[0], tid, av);
    st_kmaj(Bs[0], kpb, c0, bx, by);

    const int nIter = KE / 32;
    for (int i = 0; i < nIter; i++) {
        const int buf = i & 1, nb = buf ^ 1;
        __syncthreads();
        const int k1 = (i + 1) << 5;
        if (i + 1 < nIter) {
            const int sl = lA + (k1 >> 9) - 2;
            if ((unsigned)sl < 512u)
                ld_mmaj(av, Ah + (((size_t)(bA << 9) + sl) << 9) + (k1 & 511));
            else
                av[0] = av[1] = av[2] = av[3] = make_uint4(0, 0, 0, 0);
            ld_kmaj(bx, by, Bh, Ee, k1, kpb, bc + c0);
        }
        mma_core64h(As[buf], Bs[buf], c, g, t, wm, wn);
        if (i + 1 < nIter) {
            st_mmaj(As[nb], tid, av);
            st_kmaj(Bs[nb], kpb, c0, bx, by);
        }
    }

    float cs[16] = {0.f}, cq[16] = {0.f};
    #pragma unroll
    for (int mt = 0; mt < 4; mt++)
        #pragma unroll
        for (int i = 0; i < 2; i++) {
            const int rowo = br + wm + mt * 16 + g + 8 * i;
            const int l = rowo & 511;
            #pragma unroll
            for (int nt = 0; nt < 8; nt++) {
                const int col = bc + wn + nt * 8 + 2 * t;
                float2 bvv = *(const float2*)(kb + (size_t)l * 512 + col);
                float2 v;
                v.x = c[mt][nt][2 * i + 0] + bvv.x;
                v.y = c[mt][nt][2 * i + 1] + bvv.y;
                cs[nt * 2 + 0] += v.x; cq[nt * 2 + 0] += v.x * v.x;
                cs[nt * 2 + 1] += v.y; cq[nt * 2 + 1] += v.y * v.y;
                *(float2*)(C + (size_t)rowo * 512 + col) = v;
            }
        }
    colstats_epilogue(ssum, ssq, cs, cq, g, t, bc + wn);
}

// Fused NN GEMMs (z=0: q2 = l@wq + qb ; z=1: k2 = l@wk + kb). Col stats fused.
__global__ void __launch_bounds__(128) k_gemm_nn(const __half* __restrict__ Ah,
                                                 const __half* __restrict__ Bqh,
                                                 const __half* __restrict__ Bkh,
                                                 const float* __restrict__ biasq,
                                                 const float* __restrict__ biask,
                                                 float* __restrict__ Cq,
                                                 float* __restrict__ Ck,
                                                 float* __restrict__ stats) {
    const __half* Bh = blockIdx.z ? Bkh : Bqh;
    const float* bias = blockIdx.z ? biask : biasq;
    float* C = blockIdx.z ? Ck : Cq;
    float* ssum = stats + (blockIdx.z ? 4 * Ee : 2 * Ee);
    float* ssq = ssum + Ee;
    __shared__ uint32_t As[2][16][PADW];
    __shared__ uint32_t Bs[2][16][PADW];
    float c[4][8][4] = {{{0.f}}};
    const int tid = threadIdx.x;
    const int lane = tid & 31, wid = tid >> 5;
    const int g = lane >> 2, t = lane & 3;
    const int wm = (wid & 1) << 6, wn = (wid >> 1) << 6;
    const int br = blockIdx.y << 7, bc = blockIdx.x << 7;
    const int kpb = tid >> 5, c0 = (tid & 31) << 2;

    uint4 av[4];
    uint2 bx[4], by[4];
    ld_mmaj(av, Ah + (size_t)(br + tid) * 512);
    ld_kmaj(bx, by, Bh, 512, 0, kpb, bc + c0);
    st_mmaj(As[0], tid, av);
    st_kmaj(Bs[0], kpb, c0, bx, by);

    const int nIter = 16;
    for (int i = 0; i < nIter; i++) {
        const int buf = i & 1, nb = buf ^ 1;
        __syncthreads();
        const int k1 = (i + 1) << 5;
        if (i + 1 < nIter) {
            ld_mmaj(av, Ah + (size_t)(br + tid) * 512 + k1);
            ld_kmaj(bx, by, Bh, 512, k1, kpb, bc + c0);
        }
        mma_core64h(As[buf], Bs[buf], c, g, t, wm, wn);
        if (i + 1 < nIter) {
            st_mmaj(As[nb], tid, av);
            st_kmaj(Bs[nb], kpb, c0, bx, by);
        }
    }

    float cs[16] = {0.f}, cq[16] = {0.f};
    #pragma unroll
    for (int mt = 0; mt < 4; mt++)
        #pragma unroll
        for (int i = 0; i < 2; i++) {
            const int rowo = br + wm + mt * 16 + g + 8 * i;
            const int l = rowo & 511;
            #pragma unroll
            for (int nt = 0; nt < 8; nt++) {
                const int col = bc + wn + nt * 8 + 2 * t;
                float2 bvv = *(const float2*)(bias + (size_t)l * 512 + col);
                float2 v;
                v.x = c[mt][nt][2 * i + 0] + bvv.x;
                v.y = c[mt][nt][2 * i + 1] + bvv.y;
                cs[nt * 2 + 0] += v.x; cq[nt * 2 + 0] += v.x * v.x;
                cs[nt * 2 + 1] += v.y; cq[nt * 2 + 1] += v.y * v.y;
                *(float2*)(C + (size_t)rowo * 512 + col) = v;
            }
        }
    colstats_epilogue(ssum, ssq, cs, cq, g, t, bc + wn);
}

// Batched NT: C[k,q] = sum_e k2[k,e]*q2[q,e] + wbT. Both m-major. Row stats.
__global__ void __launch_bounds__(128) k_gemm_nt(const __half* __restrict__ Ain,
                                                 const __half* __restrict__ Bin,
                                                 const float* __restrict__ wbT,
                                                 float* __restrict__ Cout,
                                                 float* __restrict__ rsum,
                                                 float* __restrict__ rsq) {
    const int bz = blockIdx.z;
    const __half* A = Ain + (size_t)bz * Ll * Ee;
    const __half* Bm = Bin + (size_t)bz * Ll * Ee;
    float* C = Cout + (size_t)bz * Ll * Ll;
    __shared__ uint32_t As[2][16][PADW];
    __shared__ uint32_t Bs[2][16][PADW];
    float c[4][8][4] = {{{0.f}}};
    const int tid = threadIdx.x;
    const int lane = tid & 31, wid = tid >> 5;
    const int g = lane >> 2, t = lane & 3;
    const int wm = (wid & 1) << 6, wn = (wid >> 1) << 6;
    const int br = blockIdx.y << 7, bc = blockIdx.x << 7;

    uint4 av[4], bv[4];
    ld_mmaj(av, A + (size_t)(br + tid) * 512);
    ld_mmaj(bv, Bm + (size_t)(bc + tid) * 512);
    st_mmaj(As[0], tid, av);
    st_mmaj(Bs[0], tid, bv);

    const int nIter = 16;
    for (int i = 0; i < nIter; i++) {
        const int buf = i & 1, nb = buf ^ 1;
        __syncthreads();
        const int k1 = (i + 1) << 5;
        if (i + 1 < nIter) {
            ld_mmaj(av, A + (size_t)(br + tid) * 512 + k1);
            ld_mmaj(bv, Bm + (size_t)(bc + tid) * 512 + k1);
        }
        mma_core64h(As[buf], Bs[buf], c, g, t, wm, wn);
        if (i + 1 < nIter) {
            st_mmaj(As[nb], tid, av);
            st_mmaj(Bs[nb], tid, bv);
        }
    }

    float rs[8] = {0.f}, rq[8] = {0.f};
    #pragma unroll
    for (int mt = 0; mt < 4; mt++)
        #pragma unroll
        for (int i = 0; i < 2; i++) {
            const int rowo = br + wm + mt * 16 + g + 8 * i;
            #pragma unroll
            for (int nt = 0; nt < 8; nt++) {
                const int col = bc + wn + nt * 8 + 2 * t;
                float2 bv2 = *(const float2*)(wbT + (size_t)rowo * 512 + col);
                float2 v;
                v.x = c[mt][nt][2 * i + 0] + bv2.x;
                v.y = c[mt][nt][2 * i + 1] + bv2.y;
                rs[mt * 2 + i] += v.x + v.y;
                rq[mt * 2 + i] += v.x * v.x + v.y * v.y;
                *(float2*)(C + (size_t)rowo * 512 + col) = v;
            }
        }
    #pragma unroll
    for (int x = 0; x < 8; x++) {
        float s = rs[x], q = rq[x];
        s += __shfl_xor_sync(0xffffffffu, s, 1); q += __shfl_xor_sync(0xffffffffu, q, 1);
        s += __shfl_xor_sync(0xffffffffu, s, 2); q += __shfl_xor_sync(0xffffffffu, q, 2);
        if (t == 0) {
            const int rowo = br + wm + (x >> 1) * 16 + g + 8 * (x & 1);
            atomicAdd(&rsum[rowo], s);
            atomicAdd(&rsq[rowo], q);
        }
    }
}

// Batched TN: C[q,e] = sum_k wh[k,q]*lh[k,e]. Both k-major. Col stats fused.
__global__ void __launch_bounds__(128) k_gemm_tn(const __half* __restrict__ Ain,
                                                 const __half* __restrict__ Bin,
                                                 float* __restrict__ Cout,
                                                 float* __restrict__ ssum,
                                                 float* __restrict__ ssq) {
    const int bz = blockIdx.z;
    const __half* A = Ain + (size_t)bz * Ll * Ll;
    const __half* Bm = Bin + (size_t)bz * Ll * Ee;
    float* C = Cout + (size_t)bz * Ll * Ee;
    __shared__ uint32_t As[2][16][PADW];
    __shared__ uint32_t Bs[2][16][PADW];
    float c[4][8][4] = {{{0.f}}};
    const int tid = threadIdx.x;
    const int lane = tid & 31, wid = tid >> 5;
    const int g = lane >> 2, t = lane & 3;
    const int wm = (wid & 1) << 6, wn = (wid >> 1) << 6;
    const int br = blockIdx.y << 7, bc = blockIdx.x << 7;
    const int kpb = tid >> 5, c0 = (tid & 31) << 2;

    uint2 ax[4], ay[4], bx[4], by[4];
    ld_kmaj(ax, ay, A, 512, 0, kpb, br + c0);
    ld_kmaj(bx, by, Bm, 512, 0, kpb, bc + c0);
    st_kmaj(As[0], kpb, c0, ax, ay);
    st_kmaj(Bs[0], kpb, c0, bx, by);

    const int nIter = 16;
    for (int i = 0; i < nIter; i++) {
        const int buf = i & 1, nb = buf ^ 1;
        __syncthreads();
        const int k1 = (i + 1) << 5;
        if (i + 1 < nIter) {
            ld_kmaj(ax, ay, A, 512, k1, kpb, br + c0);
            ld_kmaj(bx, by, Bm, 512, k1, kpb, bc + c0);
        }
        mma_core64h(As[buf], Bs[buf], c, g, t, wm, wn);
        if (i + 1 < nIter) {
            st_kmaj(As[nb], kpb, c0, ax, ay);
            st_kmaj(Bs[nb], kpb, c0, bx, by);
        }
    }

    float cs[16] = {0.f}, cq[16] = {0.f};
    #pragma unroll
    for (int mt = 0; mt < 4; mt++)
        #pragma unroll
        for (int i = 0; i < 2; i++) {
            const int rowo = br + wm + mt * 16 + g + 8 * i;
            #pragma unroll
            for (int nt = 0; nt < 8; nt++) {
                const int col = bc + wn + nt * 8 + 2 * t;
                float2 v;
                v.x = c[mt][nt][2 * i + 0];
                v.y = c[mt][nt][2 * i + 1];
                cs[nt * 2 + 0] += v.x; cq[nt * 2 + 0] += v.x * v.x;
                cs[nt * 2 + 1] += v.y; cq[nt * 2 + 1] += v.y * v.y;
                *(float2*)(C + (size_t)rowo * 512 + col) = v;
            }
        }
    colstats_epilogue(ssum, ssq, cs, cq, g, t, bc + wn);
}

extern "C" void kernel_launch(void* const* d_in, const int* in_sizes, int n_in,
                              void* d_out, int out_size) {
    const float* m1 = (const float*)d_in[0];
    const float* f  = (const float*)d_in[1];
    const float* wq = (const float*)d_in[2];
    const float* wk = (const float*)d_in[3];
    const float* qb = (const float*)d_in[4];
    const float* kb = (const float*)d_in[5];
    const float* wb = (const float*)d_in[6];
    const float* g1 = (const float*)d_in[7];  const float* b1 = (const float*)d_in[8];
    const float* g2 = (const float*)d_in[9];  const float* b2 = (const float*)d_in[10];
    const float* g3 = (const float*)d_in[11]; const float* b3 = (const float*)d_in[12];
    const float* g4 = (const float*)d_in[13]; const float* b4 = (const float*)d_in[14];
    const float* g5 = (const float*)d_in[15]; const float* b5 = (const float*)d_in[16];

    float *pl, *pq, *pk, *pw, *po, *ps, *pwbT;
    __half *pm1h, *pfh, *pwqh, *pwkh, *plh, *pqh, *pkh, *pwh;
    cudaGetSymbolAddress((void**)&pl, g_l);
    cudaGetSymbolAddress((void**)&pq, g_q);
    cudaGetSymbolAddress((void**)&pk, g_k);
    cudaGetSymbolAddress((void**)&pw, g_w);
    cudaGetSymbolAddress((void**)&po, g_o);
    cudaGetSymbolAddress((void**)&ps, g_s);
    cudaGetSymbolAddress((void**)&pwbT, g_wbT);
    cudaGetSymbolAddress((void**)&pm1h, g_m1h);
    cudaGetSymbolAddress((void**)&pfh, g_fh);
    cudaGetSymbolAddress((void**)&pwqh, g_wqh);
    cudaGetSymbolAddress((void**)&pwkh, g_wkh);
    cudaGetSymbolAddress((void**)&plh, g_lh);
    cudaGetSymbolAddress((void**)&pqh, g_qh);
    cudaGetSymbolAddress((void**)&pkh, g_kh);
    cudaGetSymbolAddress((void**)&pwh, g_wh);

    const int T = 256, TG = 128;

    // fused pre-pass: stats zero + fp32->fp16 conversions + wb transpose
    k_prep<<<PREP_MAIN + 256, T>>>((const float4*)m1, (uint2*)pm1h,
                                   (const float4*)f, (uint2*)pfh,
                                   (const float4*)wq, (uint2*)pwqh,
                                   (const float4*)wk, (uint2*)pwkh,
                                   (float4*)ps, wb, pwbT);

    // 1) l_pre = unfold(m1) @ f + kb ; BN1+ELU -> half
    k_gemm1<<<dim3(4, 128), TG>>>(pm1h, pfh, kb, pl, ps + 0 * Ee, ps + 1 * Ee);
    k_bn_elu<true><<<2048, T>>>((const float4*)pl, plh,
                                (const float4*)(ps + 0 * Ee), (const float4*)(ps + 1 * Ee),
                                (const float4*)g1, (const float4*)b1);

    // 2) q2 / k2 ; merged BN+ELU -> half
    k_gemm_nn<<<dim3(4, 128, 2), TG>>>(plh, pwqh, pwkh, qb, kb, pq, pk, ps);
    k_bn_elu_qk<<<dim3(2048, 2), T>>>((const float4*)pq, (uint2*)pqh,
                                      (const float4*)pk, (uint2*)pkh, ps,
                                      (const float4*)g2, (const float4*)b2,
                                      (const float4*)g3, (const float4*)b3);

    // 3) wT = k2 @ q2^T + wbT ; BN4 + softmax (warp-per-row) -> half
    k_gemm_nt<<<dim3(4, 4, 32), TG>>>(pkh, pqh, pwbT, pw, ps + 8 * Ee, ps + 9 * Ee);
    k_bn_softmax<<<2048, T>>>(pw, pwh, ps + 8 * Ee, ps + 9 * Ee, g4, b4);

    // 4) out = wT^T @ l ; BN5 + ELU -> d_out (fp32)
    k_gemm_tn<<<dim3(4, 4, 32), TG>>>(pwh, plh, po, ps + 6 * Ee, ps + 7 * Ee);
    k_bn_elu<false><<<2048, T>>>((const float4*)po, d_out,
                                 (const float4*)(ps + 6 * Ee), (const float4*)(ps + 7 * Ee),
                                 (const float4*)g5, (const float4*)b5);
}